// round 14
// baseline (speedup 1.0000x reference)
#include <cuda_runtime.h>
#include <cuda_bf16.h>
#include <cstdint>

static constexpr int kB  = 4;
static constexpr int kS  = 1024;
static constexpr int kDM = 1024;
static constexpr int kH  = 16;
static constexpr int kDK = 64;
static constexpr int kBH = kB * kH;   // 64

// ---------------- scratch (static device globals; no allocation) ----------------
__device__ float g_qh [kBH * kS * kDK];
__device__ float g_kh [kBH * kS * kDK];
__device__ float g_vh [kBH * kS * kDK];
__device__ float g_att[kB * kS * kDM];

// bf16 tile buffers (SW128 tile-image layout, [bh][blk16][4096])
__device__ __nv_bfloat16 g_krh[kBH * 16 * 4096];
__device__ __nv_bfloat16 g_krl[kBH * 16 * 4096];
__device__ __nv_bfloat16 g_vrh[kBH * 16 * 4096];
__device__ __nv_bfloat16 g_kth[kBH * 16 * 4096];
__device__ __nv_bfloat16 g_ktl[kBH * 16 * 4096];
// bf16 linear [bh][s][d]
__device__ __nv_bfloat16 g_q1h[kBH * kS * kDK];
__device__ __nv_bfloat16 g_q1l[kBH * kS * kDK];
__device__ __nv_bfloat16 g_q2h[kBH * kS * kDK];
__device__ __nv_bfloat16 g_q2l[kBH * kS * kDK];

// ---------------------------------------------------------------------------
// helpers
// ---------------------------------------------------------------------------
__device__ __forceinline__ uint32_t smem_u32(const void* p) {
    uint32_t a;
    asm("{ .reg .u64 t; cvta.to.shared.u64 t, %1; cvt.u32.u64 %0, t; }" : "=r"(a) : "l"(p));
    return a;
}
__device__ __forceinline__ uint32_t pack_bf2(__nv_bfloat16 a, __nv_bfloat16 b) {
    __nv_bfloat162 t = __halves2bfloat162(a, b);
    return *reinterpret_cast<uint32_t*>(&t);
}
__device__ __forceinline__ uint32_t sw128(uint32_t o) { return o ^ ((o >> 3) & 0x70); }

#if defined(__CUDA_ARCH_FEAT_SM103_ALL) || !defined(__CUDA_ARCH__)
#define HAS_TCGEN05 1
#else
#define HAS_TCGEN05 0
#endif

#if HAS_TCGEN05
__device__ __forceinline__ void mbar_wait(uint32_t mbar, uint32_t parity) {
    asm volatile(
        "{\n\t.reg .pred P;\n\t"
        "LW%=:\n\t"
        "mbarrier.try_wait.parity.acquire.cta.shared::cta.b64 P, [%0], %1;\n\t"
        "@!P bra LW%=;\n\t}"
        :: "r"(mbar), "r"(parity) : "memory");
}

static constexpr uint32_t GE_IDESC =           // M=128, N=128
    (1u << 4) | (1u << 7) | (1u << 10) | ((128u / 8) << 17) | ((128u / 16) << 24);
static constexpr uint32_t AT_IDESC =           // M=128, N=64
    (1u << 4) | (1u << 7) | (1u << 10) | ((64u / 8) << 17) | ((128u / 16) << 24);

static constexpr uint64_t DESC_SW128 =
    (2ull << 61) | (1ull << 46) | (64ull << 32) | (1ull << 16);

__device__ __forceinline__ uint64_t mk_desc(uint32_t addr) {
    return DESC_SW128 | (uint64_t)((addr >> 4) & 0x3FFF);
}

__device__ __forceinline__ void mma_ss(uint32_t d, uint64_t ad, uint64_t bd,
                                       uint32_t idesc, bool en) {
    uint32_t e = en ? 1u : 0u;
    asm volatile(
        "{\n\t.reg .pred p;\n\t"
        "setp.ne.u32 p, %5, 0;\n\t"
        "tcgen05.mma.cta_group::1.kind::f16 [%0], %1, %2, %3, {%4, %4, %4, %4}, p;\n\t}"
        :: "r"(d), "l"(ad), "l"(bd), "r"(idesc), "r"(0u), "r"(e) : "memory");
}
__device__ __forceinline__ void mma_ts(uint32_t d, uint32_t at, uint64_t bd,
                                       uint32_t idesc, bool en) {
    uint32_t e = en ? 1u : 0u;
    asm volatile(
        "{\n\t.reg .pred p;\n\t"
        "setp.ne.u32 p, %5, 0;\n\t"
        "tcgen05.mma.cta_group::1.kind::f16 [%0], [%1], %2, %3, {%4, %4, %4, %4}, p;\n\t}"
        :: "r"(d), "r"(at), "l"(bd), "r"(idesc), "r"(0u), "r"(e) : "memory");
}

__device__ __forceinline__ void bulk_cp(uint32_t smem_dst, const void* gsrc,
                                        uint32_t bytes, uint32_t mbar) {
    asm volatile(
        "cp.async.bulk.shared::cta.global.mbarrier::complete_tx::bytes [%0], [%1], %2, [%3];"
        :: "r"(smem_dst), "l"(gsrc), "r"(bytes), "r"(mbar) : "memory");
}
__device__ __forceinline__ void mbar_expect(uint32_t mbar, uint32_t bytes) {
    asm volatile("mbarrier.arrive.expect_tx.shared.b64 _, [%0], %1;"
                 :: "r"(mbar), "r"(bytes) : "memory");
}

#define LDTM_X32(r, addr) \
    asm volatile( \
        "tcgen05.ld.sync.aligned.32x32b.x32.b32 " \
        "{%0, %1, %2, %3, %4, %5, %6, %7, " \
        " %8, %9, %10, %11, %12, %13, %14, %15, " \
        " %16, %17, %18, %19, %20, %21, %22, %23, " \
        " %24, %25, %26, %27, %28, %29, %30, %31}, [%32];" \
        : "=r"((r)[0]),  "=r"((r)[1]),  "=r"((r)[2]),  "=r"((r)[3]), \
          "=r"((r)[4]),  "=r"((r)[5]),  "=r"((r)[6]),  "=r"((r)[7]), \
          "=r"((r)[8]),  "=r"((r)[9]),  "=r"((r)[10]), "=r"((r)[11]), \
          "=r"((r)[12]), "=r"((r)[13]), "=r"((r)[14]), "=r"((r)[15]), \
          "=r"((r)[16]), "=r"((r)[17]), "=r"((r)[18]), "=r"((r)[19]), \
          "=r"((r)[20]), "=r"((r)[21]), "=r"((r)[22]), "=r"((r)[23]), \
          "=r"((r)[24]), "=r"((r)[25]), "=r"((r)[26]), "=r"((r)[27]), \
          "=r"((r)[28]), "=r"((r)[29]), "=r"((r)[30]), "=r"((r)[31]) \
        : "r"(addr))

#define TSTM_X32(addr, r) \
    asm volatile( \
        "tcgen05.st.sync.aligned.32x32b.x32.b32 [%0], " \
        "{%1, %2, %3, %4, %5, %6, %7, %8, " \
        " %9, %10, %11, %12, %13, %14, %15, %16, " \
        " %17, %18, %19, %20, %21, %22, %23, %24, " \
        " %25, %26, %27, %28, %29, %30, %31, %32};" \
        :: "r"(addr), \
           "r"((r)[0]),  "r"((r)[1]),  "r"((r)[2]),  "r"((r)[3]), \
           "r"((r)[4]),  "r"((r)[5]),  "r"((r)[6]),  "r"((r)[7]), \
           "r"((r)[8]),  "r"((r)[9]),  "r"((r)[10]), "r"((r)[11]), \
           "r"((r)[12]), "r"((r)[13]), "r"((r)[14]), "r"((r)[15]), \
           "r"((r)[16]), "r"((r)[17]), "r"((r)[18]), "r"((r)[19]), \
           "r"((r)[20]), "r"((r)[21]), "r"((r)[22]), "r"((r)[23]), \
           "r"((r)[24]), "r"((r)[25]), "r"((r)[26]), "r"((r)[27]), \
           "r"((r)[28]), "r"((r)[29]), "r"((r)[30]), "r"((r)[31]) \
        : "memory")
#endif  // HAS_TCGEN05

// convert float4 -> bf16 hi + bf16 residual, store 8B to each smem tile
__device__ __forceinline__ void store_hilo(float4 v, uint32_t hoff, uint32_t loff) {
    __nv_bfloat16 h0 = __float2bfloat16(v.x), h1 = __float2bfloat16(v.y);
    __nv_bfloat16 h2 = __float2bfloat16(v.z), h3 = __float2bfloat16(v.w);
    float r0 = v.x - __bfloat162float(h0), r1 = v.y - __bfloat162float(h1);
    float r2 = v.z - __bfloat162float(h2), r3 = v.w - __bfloat162float(h3);
    uint32_t hp0 = pack_bf2(h0, h1), hp1 = pack_bf2(h2, h3);
    uint32_t lp0 = pack_bf2(__float2bfloat16(r0), __float2bfloat16(r1));
    uint32_t lp1 = pack_bf2(__float2bfloat16(r2), __float2bfloat16(r3));
    asm volatile("st.shared.v2.b32 [%0], {%1, %2};" :: "r"(hoff), "r"(hp0), "r"(hp1) : "memory");
    asm volatile("st.shared.v2.b32 [%0], {%1, %2};" :: "r"(loff), "r"(lp0), "r"(lp1) : "memory");
}

// pack 8 floats -> uint4 of bf16 hi; and uint4 of residual lo
__device__ __forceinline__ uint4 pack_hi8(const float* f) {
    uint4 u;
    u.x = pack_bf2(__float2bfloat16(f[0]), __float2bfloat16(f[1]));
    u.y = pack_bf2(__float2bfloat16(f[2]), __float2bfloat16(f[3]));
    u.z = pack_bf2(__float2bfloat16(f[4]), __float2bfloat16(f[5]));
    u.w = pack_bf2(__float2bfloat16(f[6]), __float2bfloat16(f[7]));
    return u;
}
__device__ __forceinline__ uint4 pack_lo8(const float* f) {
    float r[8];
    #pragma unroll
    for (int i = 0; i < 8; i++)
        r[i] = f[i] - __bfloat162float(__float2bfloat16(f[i]));
    return pack_hi8(r);
}

// ---------------------------------------------------------------------------
// tc_gemm: C = A*W^T + bias, tcgen05 hi/lo (unchanged)
// ---------------------------------------------------------------------------
__global__ __launch_bounds__(256)
void tc_gemm(const float* __restrict__ A, const float* __restrict__ W,
             const float* __restrict__ bias, float* __restrict__ out, int mode)
{
    extern __shared__ char dsm[];
    const int t   = threadIdx.x;
    const int m0  = blockIdx.y * 128;
    const int n0  = blockIdx.x * 128;

#if HAS_TCGEN05
    __shared__ uint32_t s_tmem;
    __shared__ __align__(8) uint64_t s_mbar;

    const uint32_t base = (smem_u32(dsm) + 1023u) & ~1023u;
    const uint32_t ah = base, al = base + 16384, bhs = base + 32768, bls = base + 49152;
    const int wid = t >> 5;

    if (wid == 0) {
        asm volatile("tcgen05.alloc.cta_group::1.sync.aligned.shared::cta.b32 [%0], %1;"
                     :: "r"(smem_u32(&s_tmem)), "r"(128u) : "memory");
        asm volatile("tcgen05.relinquish_alloc_permit.cta_group::1.sync.aligned;");
    }
    if (t == 0)
        asm volatile("mbarrier.init.shared.b64 [%0], 1;" :: "r"(smem_u32(&s_mbar)) : "memory");
    __syncthreads();
    const uint32_t tmem = s_tmem;
    const uint32_t mbar = smem_u32(&s_mbar);

    const int ty = t >> 4, c4 = t & 15;
    const float* Ap = A + (size_t)(m0 + ty) * 1024 + c4 * 4;
    const float* Wp = W + (size_t)(n0 + ty) * 1024 + c4 * 4;

    int chunk = 0;
    for (int k0 = 0; k0 < 1024; k0 += 64, ++chunk) {
        float4 av[8], wv[8];
        #pragma unroll
        for (int i = 0; i < 8; i++) {
            av[i] = *(const float4*)(Ap + (size_t)(16 * i) * 1024 + k0);
            wv[i] = *(const float4*)(Wp + (size_t)(16 * i) * 1024 + k0);
        }
        if (chunk > 0) mbar_wait(mbar, (chunk - 1) & 1);
        #pragma unroll
        for (int i = 0; i < 8; i++) {
            uint32_t off = sw128((uint32_t)((ty + 16 * i) * 128 + c4 * 8));
            store_hilo(av[i], ah + off, al + off);
            store_hilo(wv[i], bhs + off, bls + off);
        }
        asm volatile("fence.proxy.async.shared::cta;" ::: "memory");
        __syncthreads();
        if (t == 0) {
            const uint64_t dah = mk_desc(ah),  dal = mk_desc(al);
            const uint64_t dbh = mk_desc(bhs), dbl = mk_desc(bls);
            #pragma unroll
            for (int ks = 0; ks < 4; ks++) {
                mma_ss(tmem, dah + 2 * ks, dbh + 2 * ks, GE_IDESC, !(chunk == 0 && ks == 0));
                mma_ss(tmem, dah + 2 * ks, dbl + 2 * ks, GE_IDESC, true);
                mma_ss(tmem, dal + 2 * ks, dbh + 2 * ks, GE_IDESC, true);
            }
            asm volatile(
                "tcgen05.commit.cta_group::1.mbarrier::arrive::one.shared::cluster.b64 [%0];"
                :: "r"(mbar) : "memory");
        }
    }
    mbar_wait(mbar, (16 - 1) & 1);
    __syncthreads();
    asm volatile("tcgen05.fence::after_thread_sync;" ::: "memory");

    if (wid < 4) {
        const int lane = t & 31;
        const int gr = m0 + wid * 32 + lane;
        for (int cb = 0; cb < 128; cb += 32) {
            uint32_t regs[32];
            LDTM_X32(regs, tmem + cb);
            asm volatile("tcgen05.wait::ld.sync.aligned;" ::: "memory");
            if (mode == 0) {
                float* op = out + (size_t)gr * 1024 + n0 + cb;
                #pragma unroll
                for (int c = 0; c < 32; c++)
                    op[c] = __uint_as_float(regs[c]) + bias[n0 + cb + c];
            } else {
                const int b = gr >> 10, s = gr & 1023;
                #pragma unroll
                for (int c = 0; c < 32; c++) {
                    const int gc = n0 + cb + c;
                    const int h = gc >> 6, d = gc & 63;
                    out[(((size_t)(b * kH + h)) * kS + s) * kDK + d] =
                        __uint_as_float(regs[c]) + bias[gc];
                }
            }
        }
    }
    __syncthreads();
    if (wid == 0)
        asm volatile("tcgen05.dealloc.cta_group::1.sync.aligned.b32 %0, %1;"
                     :: "r"(tmem), "r"(128u));
#else
    float* As = (float*)dsm;
    float* Bs = As + 16 * 128;
    const int tx = t & 15, ty = t >> 4;
    const int lm = t & 127;
    const int kb = (t >> 7) * 8;
    float acc[8][8];
    #pragma unroll
    for (int i = 0; i < 8; i++)
        #pragma unroll
        for (int j = 0; j < 8; j++) acc[i][j] = 0.f;
    for (int k0 = 0; k0 < 1024; k0 += 16) {
        const float4* Ag = (const float4*)(A + (size_t)(m0 + lm) * 1024 + k0 + kb);
        const float4* Wg = (const float4*)(W + (size_t)(n0 + lm) * 1024 + k0 + kb);
        float4 a0 = Ag[0], a1 = Ag[1];
        float4 b0 = Wg[0], b1 = Wg[1];
        As[(kb+0)*128+lm]=a0.x; As[(kb+1)*128+lm]=a0.y; As[(kb+2)*128+lm]=a0.z; As[(kb+3)*128+lm]=a0.w;
        As[(kb+4)*128+lm]=a1.x; As[(kb+5)*128+lm]=a1.y; As[(kb+6)*128+lm]=a1.z; As[(kb+7)*128+lm]=a1.w;
        Bs[(kb+0)*128+lm]=b0.x; Bs[(kb+1)*128+lm]=b0.y; Bs[(kb+2)*128+lm]=b0.z; Bs[(kb+3)*128+lm]=b0.w;
        Bs[(kb+4)*128+lm]=b1.x; Bs[(kb+5)*128+lm]=b1.y; Bs[(kb+6)*128+lm]=b1.z; Bs[(kb+7)*128+lm]=b1.w;
        __syncthreads();
        #pragma unroll
        for (int kk = 0; kk < 16; kk++) {
            float af[8], bf[8];
            #pragma unroll
            for (int i = 0; i < 8; i++) af[i] = As[kk*128 + ty + 16*i];
            #pragma unroll
            for (int j = 0; j < 8; j++) bf[j] = Bs[kk*128 + tx + 16*j];
            #pragma unroll
            for (int i = 0; i < 8; i++)
                #pragma unroll
                for (int j = 0; j < 8; j++) acc[i][j] += af[i] * bf[j];
        }
        __syncthreads();
    }
    #pragma unroll
    for (int i = 0; i < 8; i++) {
        const int r = m0 + ty + 16*i;
        #pragma unroll
        for (int j = 0; j < 8; j++) {
            const int c = n0 + tx + 16*j;
            float v = acc[i][j] + bias[c];
            if (mode == 0) out[(size_t)r * 1024 + c] = v;
            else {
                int b = r >> 10, s = r & 1023, h = c >> 6, d = c & 63;
                out[(((size_t)(b * kH + h)) * kS + s) * kDK + d] = v;
            }
        }
    }
#endif
}

// ---------------------------------------------------------------------------
// conv_kv: FFMA producer (proven R10 version)
// ---------------------------------------------------------------------------
__global__ __launch_bounds__(256)
void conv_kv(const float* __restrict__ Kh, const float* __restrict__ Vh,
             const float* __restrict__ Wkl, const float* __restrict__ bkl,
             const float* __restrict__ Wvl, const float* __restrict__ bvl,
             __nv_bfloat16* __restrict__ krh, __nv_bfloat16* __restrict__ krl,
             __nv_bfloat16* __restrict__ vrh,
             __nv_bfloat16* __restrict__ kth, __nv_bfloat16* __restrict__ ktl)
{
    extern __shared__ float fs[];
    float* W1 = fs;
    float* W2 = W1 + 4096;
    float* Xs = W2 + 4096;
    float* St = Xs + 4096;

    const int t  = threadIdx.x;
    const int tx = t & 15, ty = t >> 4;
    const int r0 = blockIdx.x * 64;
    const int lr = t & 63;
    const int kb = (t >> 6) * 16;
    const int bh = r0 >> 10, blkid = (r0 >> 6) & 15;
    const size_t tbase = ((size_t)bh * 16 + blkid) * 4096;
    const int wr = t >> 2, wq = t & 3;

    #pragma unroll
    for (int q = 0; q < 4; q++) {
        float4 w1 = *(const float4*)(Wkl + (size_t)lr * 64 + kb + 4*q);
        float4 w2 = *(const float4*)(Wvl + (size_t)lr * 64 + kb + 4*q);
        W1[(kb+4*q+0)*64+lr]=w1.x; W1[(kb+4*q+1)*64+lr]=w1.y; W1[(kb+4*q+2)*64+lr]=w1.z; W1[(kb+4*q+3)*64+lr]=w1.w;
        W2[(kb+4*q+0)*64+lr]=w2.x; W2[(kb+4*q+1)*64+lr]=w2.y; W2[(kb+4*q+2)*64+lr]=w2.z; W2[(kb+4*q+3)*64+lr]=w2.w;
    }

    // ---- pass 0: Kh -> kT tiles + kr tiles ----
    #pragma unroll
    for (int q = 0; q < 4; q++) {
        float4 x = *(const float4*)(Kh + (size_t)(r0 + lr) * 64 + kb + 4*q);
        Xs[(kb+4*q+0)*64+lr]=x.x; Xs[(kb+4*q+1)*64+lr]=x.y;
        Xs[(kb+4*q+2)*64+lr]=x.z; Xs[(kb+4*q+3)*64+lr]=x.w;
    }
    __syncthreads();

    {
        const int d = t & 63, seg = t >> 6;
        float f[16];
        #pragma unroll
        for (int i = 0; i < 16; i++) f[i] = Xs[d * 64 + seg * 16 + i];
        uint32_t o0 = (uint32_t)(d * 128 + seg * 32);
        uint32_t s0 = sw128(o0), s1 = sw128(o0 + 16);
        char* th = (char*)(kth + tbase);
        char* tl = (char*)(ktl + tbase);
        *(uint4*)(th + s0) = pack_hi8(f);     *(uint4*)(th + s1) = pack_hi8(f + 8);
        *(uint4*)(tl + s0) = pack_lo8(f);     *(uint4*)(tl + s1) = pack_lo8(f + 8);
    }

    {
        float acc[4][4];
        #pragma unroll
        for (int i = 0; i < 4; i++)
            #pragma unroll
            for (int j = 0; j < 4; j++) acc[i][j] = 0.f;
        #pragma unroll 16
        for (int kk = 0; kk < 64; kk++) {
            float af[4], bf[4];
            #pragma unroll
            for (int i = 0; i < 4; i++) af[i] = Xs[kk*64 + ty + 16*i];
            #pragma unroll
            for (int j = 0; j < 4; j++) bf[j] = W1[kk*64 + tx + 16*j];
            #pragma unroll
            for (int i = 0; i < 4; i++)
                #pragma unroll
                for (int j = 0; j < 4; j++) acc[i][j] += af[i] * bf[j];
        }
        #pragma unroll
        for (int i = 0; i < 4; i++)
            #pragma unroll
            for (int j = 0; j < 4; j++)
                St[(ty + 16*i) * 64 + tx + 16*j] = fmaxf(acc[i][j] + bkl[tx + 16*j], 0.f);
    }
    __syncthreads();
    {
        float f[16];
        #pragma unroll
        for (int i = 0; i < 16; i++) f[i] = St[wr * 64 + wq * 16 + i];
        uint32_t o0 = (uint32_t)(wr * 128 + wq * 32);
        uint32_t s0 = sw128(o0), s1 = sw128(o0 + 16);
        char* th = (char*)(krh + tbase);
        char* tl = (char*)(krl + tbase);
        *(uint4*)(th + s0) = pack_hi8(f);     *(uint4*)(th + s1) = pack_hi8(f + 8);
        *(uint4*)(tl + s0) = pack_lo8(f);     *(uint4*)(tl + s1) = pack_lo8(f + 8);
    }
    __syncthreads();

    // ---- pass 1: Vh -> vrh tiles ----
    #pragma unroll
    for (int q = 0; q < 4; q++) {
        float4 x = *(const float4*)(Vh + (size_t)(r0 + lr) * 64 + kb + 4*q);
        Xs[(kb+4*q+0)*64+lr]=x.x; Xs[(kb+4*q+1)*64+lr]=x.y;
        Xs[(kb+4*q+2)*64+lr]=x.z; Xs[(kb+4*q+3)*64+lr]=x.w;
    }
    __syncthreads();
    {
        float acc[4][4];
        #pragma unroll
        for (int i = 0; i < 4; i++)
            #pragma unroll
            for (int j = 0; j < 4; j++) acc[i][j] = 0.f;
        #pragma unroll 16
        for (int kk = 0; kk < 64; kk++) {
            float af[4], bf[4];
            #pragma unroll
            for (int i = 0; i < 4; i++) af[i] = Xs[kk*64 + ty + 16*i];
            #pragma unroll
            for (int j = 0; j < 4; j++) bf[j] = W2[kk*64 + tx + 16*j];
            #pragma unroll
            for (int i = 0; i < 4; i++)
                #pragma unroll
                for (int j = 0; j < 4; j++) acc[i][j] += af[i] * bf[j];
        }
        #pragma unroll
        for (int i = 0; i < 4; i++)
            #pragma unroll
            for (int j = 0; j < 4; j++)
                St[(ty + 16*i) * 64 + tx + 16*j] = fmaxf(acc[i][j] + bvl[tx + 16*j], 0.f);
    }
    __syncthreads();
    {
        float f[16];
        #pragma unroll
        for (int i = 0; i < 16; i++) f[i] = St[wr * 64 + wq * 16 + i];
        uint32_t o0 = (uint32_t)(wr * 128 + wq * 32);
        uint32_t s0 = sw128(o0), s1 = sw128(o0 + 16);
        char* th = (char*)(vrh + tbase);
        *(uint4*)(th + s0) = pack_hi8(f);     *(uint4*)(th + s1) = pack_hi8(f + 8);
    }
}

// ---------------------------------------------------------------------------
// fused_q: FFMA producer (proven R10 version)
// ---------------------------------------------------------------------------
__global__ __launch_bounds__(256)
void fused_q(const float* __restrict__ X,
             const float* __restrict__ Wql, const float* __restrict__ bql,
             const float* __restrict__ Wel, const float* __restrict__ bel,
             const float* __restrict__ Wq2, const float* __restrict__ bq2,
             __nv_bfloat16* __restrict__ q1h, __nv_bfloat16* __restrict__ q1l,
             __nv_bfloat16* __restrict__ q2h, __nv_bfloat16* __restrict__ q2l)
{
    extern __shared__ float fs[];
    float* Xs = fs;
    float* Ys = Xs + 4096;
    float* W1 = Ys + 64 * 65;
    float* W2 = W1 + 4096;
    float* W3 = W2 + 4096;
    float* St = W3 + 4096;

    const int t  = threadIdx.x;
    const int tx = t & 15, ty = t >> 4;
    const int r0 = blockIdx.x * 64;
    const int lr = t & 63;
    const int kb = (t >> 6) * 16;
    const int wr = t >> 2, wq = t & 3;

    #pragma unroll
    for (int q = 0; q < 4; q++) {
        float4 w1 = *(const float4*)(Wql + (size_t)lr * 64 + kb + 4*q);
        float4 w2 = *(const float4*)(Wel + (size_t)lr * 64 + kb + 4*q);
        float4 w3 = *(const float4*)(Wq2 + (size_t)lr * 64 + kb + 4*q);
        W1[(kb+4*q+0)*64+lr]=w1.x; W1[(kb+4*q+1)*64+lr]=w1.y; W1[(kb+4*q+2)*64+lr]=w1.z; W1[(kb+4*q+3)*64+lr]=w1.w;
        W2[(kb+4*q+0)*64+lr]=w2.x; W2[(kb+4*q+1)*64+lr]=w2.y; W2[(kb+4*q+2)*64+lr]=w2.z; W2[(kb+4*q+3)*64+lr]=w2.w;
        W3[(kb+4*q+0)*64+lr]=w3.x; W3[(kb+4*q+1)*64+lr]=w3.y; W3[(kb+4*q+2)*64+lr]=w3.z; W3[(kb+4*q+3)*64+lr]=w3.w;
        float4 x = *(const float4*)(X + (size_t)(r0 + lr) * 64 + kb + 4*q);
        Xs[(kb+4*q+0)*64+lr]=x.x; Xs[(kb+4*q+1)*64+lr]=x.y; Xs[(kb+4*q+2)*64+lr]=x.z; Xs[(kb+4*q+3)*64+lr]=x.w;
    }
    __syncthreads();

    // stage 1: q1a -> Ys
    {
        float acc[4][4];
        #pragma unroll
        for (int i = 0; i < 4; i++)
            #pragma unroll
            for (int j = 0; j < 4; j++) acc[i][j] = 0.f;
        #pragma unroll 16
        for (int kk = 0; kk < 64; kk++) {
            float af[4], bf[4];
            #pragma unroll
            for (int i = 0; i < 4; i++) af[i] = Xs[kk*64 + ty + 16*i];
            #pragma unroll
            for (int j = 0; j < 4; j++) bf[j] = W1[kk*64 + tx + 16*j];
            #pragma unroll
            for (int i = 0; i < 4; i++)
                #pragma unroll
                for (int j = 0; j < 4; j++) acc[i][j] += af[i] * bf[j];
        }
        #pragma unroll
        for (int i = 0; i < 4; i++)
            #pragma unroll
            for (int j = 0; j < 4; j++)
                Ys[(tx + 16*j) * 65 + ty + 16*i] = fmaxf(acc[i][j] + bql[tx + 16*j], 0.f);
    }

    // q2 -> St -> q2h/q2l
    {
        float acc[4][4];
        #pragma unroll
        for (int i = 0; i < 4; i++)
            #pragma unroll
            for (int j = 0; j < 4; j++) acc[i][j] = 0.f;
        #pragma unroll 16
        for (int kk = 0; kk < 64; kk++) {
            float af[4], bf[4];
            #pragma unroll
            for (int i = 0; i < 4; i++) af[i] = Xs[kk*64 + ty + 16*i];
            #pragma unroll
            for (int j = 0; j < 4; j++) bf[j] = W3[kk*64 + tx + 16*j];
            #pragma unroll
            for (int i = 0; i < 4; i++)
                #pragma unroll
                for (int j = 0; j < 4; j++) acc[i][j] += af[i] * bf[j];
        }
        __syncthreads();
        #pragma unroll
        for (int i = 0; i < 4; i++)
            #pragma unroll
            for (int j = 0; j < 4; j++)
                St[(ty + 16*i) * 64 + tx + 16*j] = fmaxf(acc[i][j] + bq2[tx + 16*j], 0.f);
    }
    __syncthreads();
    {
        float f[16];
        #pragma unroll
        for (int i = 0; i < 16; i++) f[i] = St[wr * 64 + wq * 16 + i];
        uint4* dh = (uint4*)(q2h + (size_t)(r0 + wr) * 64 + wq * 16);
        uint4* dl = (uint4*)(q2l + (size_t)(r0 + wr) * 64 + wq * 16);
        dh[0] = pack_hi8(f); dh[1] = pack_hi8(f + 8);
        dl[0] = pack_lo8(f); dl[1] = pack_lo8(f + 8);
    }
    __syncthreads();

    // q1 from Ys -> St -> q1h/q1l
    {
        float acc[4][4];
        #pragma unroll
        for (int i = 0; i < 4; i++)
            #pragma unroll
            for (int j = 0; j < 4; j++) acc[i][j] = 0.f;
        #pragma unroll 16
        for (int kk = 0; kk < 64; kk++) {
            float af[4], bf[4];
            #pragma unroll
            for (int i = 0; i < 4; i++) af[i] = Ys[kk*65 + ty + 16*i];
            #pragma unroll
            for (int j = 0; j < 4; j++) bf[j] = W2[kk*64 + tx + 16*j];
            #pragma unroll
            for (int i = 0; i < 4; i++)
                #pragma unroll
                for (int j = 0; j < 4; j++) acc[i][j] += af[i] * bf[j];
        }
        #pragma unroll
        for (int i = 0; i < 4; i++)
            #pragma unroll
            for (int j = 0; j < 4; j++)
                St[(ty + 16*i) * 64 + tx + 16*j] = fmaxf(acc[i][j] + bel[tx + 16*j], 0.f);
    }
    __syncthreads();
    {
        float f[16];
        #pragma unroll
        for (int i = 0; i < 16; i++) f[i] = St[wr * 64 + wq * 16 + i];
        uint4* dh = (uint4*)(q1h + (size_t)(r0 + wr) * 64 + wq * 16);
        uint4* dl = (uint4*)(q1l + (size_t)(r0 + wr) * 64 + wq * 16);
        dh[0] = pack_hi8(f); dh[1] = pack_hi8(f + 8);
        dl[0] = pack_lo8(f); dl[1] = pack_lo8(f + 8);
    }
}

// ---------------------------------------------------------------------------
// attn v7: 256 threads — thread t owns (row = t&127, col half = t>>7, 32 cols).
// 16 warps/SM at 2 CTAs -> better latency hiding; per-thread softmax work halved.
// Row max/sum combined across halves via smem exchange.
// TMEM (256): Q1H@0 Q1L@32 Q2H@64 Q2L@96 | TQV@128 (QV->PK) | TS@192 (S)
// smem: 2 stages (80KB) + Pl (16KB) + red (1KB); Ph aliased into stage.
// ---------------------------------------------------------------------------
__global__ __launch_bounds__(256, 2)
void attn_tc(const __nv_bfloat16* __restrict__ q1h, const __nv_bfloat16* __restrict__ q1l,
             const __nv_bfloat16* __restrict__ q2h, const __nv_bfloat16* __restrict__ q2l,
             const __nv_bfloat16* __restrict__ krh, const __nv_bfloat16* __restrict__ krl,
             const __nv_bfloat16* __restrict__ vrh,
             const __nv_bfloat16* __restrict__ kth, const __nv_bfloat16* __restrict__ ktl,
             const int* __restrict__ mask, float* __restrict__ outg)
{
    const int t  = threadIdx.x;
    const int bh = blockIdx.y;
    const int q0 = blockIdx.x * 128;
    const int b  = bh >> 4, h = bh & 15;

#if HAS_TCGEN05
    extern __shared__ char dsm[];
    __shared__ uint32_t s_tmem;
    __shared__ __align__(8) uint64_t s_mb[5];   // 0:s 1:qv 2:pk 3:ld0 4:ld1

    const uint32_t base = (smem_u32(dsm) + 1023u) & ~1023u;
    const uint32_t stg[2] = { base, base + 40960 };
    const uint32_t Pl = base + 81920;
    float* red = (float*)(dsm + (Pl + 16384 - smem_u32(dsm)));   // 256 floats

    const int wid = t >> 5;
    const int row = t & 127, half = t >> 7;
    if (wid == 0) {
        asm volatile("tcgen05.alloc.cta_group::1.sync.aligned.shared::cta.b32 [%0], %1;"
                     :: "r"(smem_u32(&s_tmem)), "r"(256u) : "memory");
        asm volatile("tcgen05.relinquish_alloc_permit.cta_group::1.sync.aligned;");
    }
    if (t == 0) {
        #pragma unroll
        for (int i = 0; i < 5; i++)
            asm volatile("mbarrier.init.shared.b64 [%0], 1;"
                         :: "r"(smem_u32(&s_mb[i])) : "memory");
    }
    __syncthreads();
    const uint32_t tmem = s_tmem;
    const uint32_t mb_s  = smem_u32(&s_mb[0]);
    const uint32_t mb_qv = smem_u32(&s_mb[1]);
    const uint32_t mb_pk = smem_u32(&s_mb[2]);
    const uint32_t mb_ld[2] = { smem_u32(&s_mb[3]), smem_u32(&s_mb[4]) };
    const uint32_t Q1H = tmem, Q1L = tmem + 32, Q2H = tmem + 64, Q2L = tmem + 96;
    const uint32_t TQV = tmem + 128, TS = tmem + 192;
    const uint32_t wof = ((uint32_t)(wid & 3)) << 21;

    const size_t tb = (size_t)bh * 16;

    if (t == 0) {
        asm volatile("fence.proxy.async.shared::cta;" ::: "memory");
        #pragma unroll
        for (int s = 0; s < 2; s++) {
            mbar_expect(mb_ld[s], 40960);
            const size_t off = (tb + s) * 4096;
            bulk_cp(stg[s] + 0,     (const char*)(krh + off), 8192, mb_ld[s]);
            bulk_cp(stg[s] + 8192,  (const char*)(krl + off), 8192, mb_ld[s]);
            bulk_cp(stg[s] + 16384, (const char*)(vrh + off), 8192, mb_ld[s]);
            bulk_cp(stg[s] + 24576, (const char*)(kth + off), 8192, mb_ld[s]);
            bulk_cp(stg[s] + 32768, (const char*)(ktl + off), 8192, mb_ld[s]);
        }
    }

    // upload q rows to TMEM: warps 0-3 do q1 (row t), warps 4-7 do q2 (row t-128)
    {
        uint32_t r[32];
        if (half == 0) {
            const uint4* p = (const uint4*)(q1h + ((size_t)bh * kS + q0 + row) * kDK);
            #pragma unroll
            for (int i = 0; i < 8; i++) { uint4 v = p[i];
                r[4*i]=v.x; r[4*i+1]=v.y; r[4*i+2]=v.z; r[4*i+3]=v.w; }
            TSTM_X32(Q1H + wof, r);
            p = (const uint4*)(q1l + ((size_t)bh * kS + q0 + row) * kDK);
            #pragma unroll
            for (int i = 0; i < 8; i++) { uint4 v = p[i];
                r[4*i]=v.x; r[4*i+1]=v.y; r[4*i+2]=v.z; r[4*i+3]=v.w; }
            TSTM_X32(Q1L + wof, r);
        } else {
            const uint4* p = (const uint4*)(q2h + ((size_t)bh * kS + q0 + row) * kDK);
            #pragma unroll
            for (int i = 0; i < 8; i++) { uint4 v = p[i];
                r[4*i]=v.x; r[4*i+1]=v.y; r[4*i+2]=v.z; r[4*i+3]=v.w; }
            TSTM_X32(Q2H + wof, r);
            p = (const uint4*)(q2l + ((size_t)bh * kS + q0 + row) * kDK);
            #pragma unroll
            for (int i = 0; i < 8; i++) { uint4 v = p[i];
                r[4*i]=v.x; r[4*i+1]=v.y; r[4*i+2]=v.z; r[4*i+3]=v.w; }
            TSTM_X32(Q2L + wof, r);
        }
        asm volatile("tcgen05.wait::st.sync.aligned;" ::: "memory");
    }
    asm volatile("tcgen05.fence::before_thread_sync;" ::: "memory");
    __syncthreads();

    // issue S(0) and QV(0)
    if (t == 0) {
        asm volatile("tcgen05.fence::after_thread_sync;" ::: "memory");
        mbar_wait(mb_ld[0], 0);
        const uint64_t dkh = mk_desc(stg[0]), dkl = mk_desc(stg[0] + 8192);
        const uint64_t dvh = mk_desc(stg[0] + 16384);
        #pragma unroll
        for (int ks = 0; ks < 4; ks++) {
            mma_ts(TS,  Q1H + ks*8, dkh + 2*ks, AT_IDESC, ks > 0);
            mma_ts(TS,  Q1H + ks*8, dkl + 2*ks, AT_IDESC, true);
            mma_ts(TS,  Q1L + ks*8, dkh + 2*ks, AT_IDESC, true);
        }
        asm volatile(
            "tcgen05.commit.cta_group::1.mbarrier::arrive::one.shared::cluster.b64 [%0];"
            :: "r"(mb_s) : "memory");
        #pragma unroll
        for (int ks = 0; ks < 4; ks++) {
            mma_ts(TQV, Q2H + ks*8, dvh + 2*ks, AT_IDESC, ks > 0);
            mma_ts(TQV, Q2L + ks*8, dvh + 2*ks, AT_IDESC, true);
        }
        asm volatile(
            "tcgen05.commit.cta_group::1.mbarrier::arrive::one.shared::cluster.b64 [%0];"
            :: "r"(mb_qv) : "memory");
    }

    float out[32];
    #pragma unroll
    for (int c = 0; c < 32; c++) out[c] = 0.f;
    float m_i = -1e30f, l_i = 0.f;

    for (int blk = 0; blk < 16; blk++) {
        const int st = blk & 1;
        const int k0 = blk * 64;
        const uint32_t Ph = stg[st];

        mbar_wait(mb_s, blk & 1);
        asm volatile("tcgen05.fence::after_thread_sync;" ::: "memory");

        uint32_t sr[32];
        LDTM_X32(sr, TS + half * 32);

        // mask loads overlap the TMEM read latency (32 ints)
        int4 mreg[8];
        const int4* mp = (const int4*)(mask + (size_t)b * kS * kS
                                       + (size_t)(q0 + row) * kS + k0 + half * 32);
        #pragma unroll
        for (int j4 = 0; j4 < 8; j4++) mreg[j4] = mp[j4];

        asm volatile("tcgen05.wait::ld.sync.aligned;" ::: "memory");

        #pragma unroll
        for (int j4 = 0; j4 < 8; j4++) {
            int4 mv = mreg[j4];
            if (mv.x == 0) sr[4*j4+0] = __float_as_uint(-1.0e9f);
            if (mv.y == 0) sr[4*j4+1] = __float_as_uint(-1.0e9f);
            if (mv.z == 0) sr[4*j4+2] = __float_as_uint(-1.0e9f);
            if (mv.w == 0) sr[4*j4+3] = __float_as_uint(-1.0e9f);
        }

        float pmax = -1e30f;
        #pragma unroll
        for (int j = 0; j < 32; j++) pmax = fmaxf(pmax, __uint_as_float(sr[j]));
        red[half * 128 + row] = pmax;
        __syncthreads();   // (A) exchange partial max
        const float rmax = fmaxf(red[row], red[128 + row]);
        const float mnew = fmaxf(m_i, rmax);
        const float sc   = __expf(m_i - mnew);

        mbar_wait(mb_qv, blk & 1);
        asm volatile("tcgen05.fence::after_thread_sync;" ::: "memory");

        uint32_t qr[32];
        LDTM_X32(qr, TQV + half * 32);
        asm volatile("tcgen05.wait::ld.sync.aligned;" ::: "memory");

        float psum = 0.f;
        #pragma unroll
        for (int j = 0; j < 32; j++) {
            float p = __expf(__uint_as_float(sr[j]) - mnew);
            psum += p;
            sr[j] = __float_as_uint(p * __uint_as_float(qr[j]));
        }
        red[half * 128 + row] = psum;

        // P hi/lo -> smem (cols half*32..+31 of row)
        #pragma unroll
        for (int c = 0; c < 4; c++) {
            float f[8];
            #pragma unroll
            for (int j = 0; j < 8; j++) f[j] = __uint_as_float(sr[8*c + j]);
            uint4 uh = pack_hi8(f);
            uint4 ul = pack_lo8(f);
            uint32_t off = sw128((uint32_t)(row * 128 + half * 64 + c * 16));
            asm volatile("st.shared.v4.b32 [%0], {%1,%2,%3,%4};"
                         :: "r"(Ph + off), "r"(uh.x), "r"(uh.y), "r"(uh.z), "r"(uh.w) : "memory");
            asm volatile("st.shared.v4.b32 [%0], {%1,%2,%3,%4};"
                         :: "r"(Pl + off), "r"(ul.x), "r"(ul.y), "r"(ul.z), "r"(ul.w) : "memory");
        }
        if (sc < 1.0f) {
            #pragma unroll
            for (int c = 0; c < 32; c++) out[c] *= sc;
        }

        asm volatile("tcgen05.fence::before_thread_sync;" ::: "memory");
        asm volatile("fence.proxy.async.shared::cta;" ::: "memory");
        __syncthreads();   // (B) publish P + partial sums

        l_i = l_i * sc + red[row] + red[128 + row];
        m_i = mnew;

        if (t == 0) {
            asm volatile("tcgen05.fence::after_thread_sync;" ::: "memory");
            // PK(blk) -> TQV (QV consumed)
            const uint64_t dPh = mk_desc(Ph), dPl = mk_desc(Pl);
            const uint64_t dth = mk_desc(stg[st] + 24576), dtl = mk_desc(stg[st] + 32768);
            #pragma unroll
            for (int ks = 0; ks < 4; ks++) {
                mma_ss(TQV, dPh + 2*ks, dth + 2*ks, AT_IDESC, ks > 0);
                mma_ss(TQV, dPh + 2*ks, dtl + 2*ks, AT_IDESC, true);
                mma_ss(TQV, dPl + 2*ks, dth + 2*ks, AT_IDESC, true);
            }
            asm volatile(
                "tcgen05.commit.cta_group::1.mbarrier::arrive::one.shared::cluster.b64 [%0];"
                :: "r"(mb_pk) : "memory");
            // early S(blk+1) -> TS
            if (blk + 1 < 16) {
                mbar_wait(mb_ld[1 - st], ((blk + 1) >> 1) & 1);
                const uint32_t sb = stg[1 - st];
                const uint64_t dkh = mk_desc(sb), dkl = mk_desc(sb + 8192);
                #pragma unroll
                for (int ks = 0; ks < 4; ks++) {
                    mma_ts(TS, Q1H + ks*8, dkh + 2*ks, AT_IDESC, ks > 0);
                    mma_ts(TS, Q1H + ks*8, dkl + 2*ks, AT_IDESC, true);
                    mma_ts(TS, Q1L + ks*8, dkh + 2*ks, AT_IDESC, true);
                }
                asm volatile(
                    "tcgen05.commit.cta_group::1.mbarrier::arrive::one.shared::cluster.b64 [%0];"
                    :: "r"(mb_s) : "memory");
            }
        }
        mbar_wait(mb_pk, blk & 1);
        asm volatile("tcgen05.fence::after_thread_sync;" ::: "memory");

        uint32_t pr[32];
        LDTM_X32(pr, TQV + half * 32);
        asm volatile("tcgen05.wait::ld.sync.aligned;" ::: "memory");
        asm volatile("tcgen05.fence::before_thread_sync;" ::: "memory");
        __syncthreads();   // (C) PK fully read before reuse

        if (t == 0) {
            // refill this stage for blk+2 (Ph area dead after PK read)
            if (blk + 2 < 16) {
                mbar_expect(mb_ld[st], 40960);
                const size_t off = (tb + blk + 2) * 4096;
                bulk_cp(stg[st] + 0,     (const char*)(krh + off), 8192, mb_ld[st]);
                bulk_cp(stg[st] + 8192,  (const char*)(krl + off), 8192, mb_ld[st]);
                bulk_cp(stg[st] + 16384, (const char*)(vrh + off), 8192, mb_ld[st]);
                bulk_cp(stg[st] + 24576, (const char*)(kth + off), 8192, mb_ld[st]);
                bulk_cp(stg[st] + 32768, (const char*)(ktl + off), 8192, mb_ld[st]);
            }
            // QV(blk+1) -> TQV (PK consumed)
            if (blk + 1 < 16) {
                asm volatile("tcgen05.fence::after_thread_sync;" ::: "memory");
                const uint64_t dvh = mk_desc(stg[1 - st] + 16384);
                #pragma unroll
                for (int ks = 0; ks < 4; ks++) {
                    mma_ts(TQV, Q2H + ks*8, dvh + 2*ks, AT_IDESC, ks > 0);
                    mma_ts(TQV, Q2L + ks*8, dvh + 2*ks, AT_IDESC, true);
                }
                asm volatile(
                    "tcgen05.commit.cta_group::1.mbarrier::arrive::one.shared::cluster.b64 [%0];"
                    :: "r"(mb_qv) : "memory");
            }
        }

        #pragma unroll
        for (int j = 0; j < 32; j++) out[j] += __uint_as_float(pr[j]);
    }

    const float inv = 1.0f / l_i;
    float4* op = (float4*)(outg + ((size_t)b * kS + q0 + row) * kDM + h * 64 + half * 32);
    #pragma unroll
    for (int c4 = 0; c4 < 8; c4++) {
        float4 v;
        v.x = out[4*c4+0] * inv; v.y = out[4*c4+1] * inv;
        v.z = out[4*c4+2] * inv; v.w = out[4*c4+3] * inv;
        op[c4] = v;
    }
    __syncthreads();
    if (wid == 0)
        asm volatile("tcgen05.dealloc.cta_group::1.sync.aligned.b32 %0, %1;"
                     :: "r"(tmem), "r"(256u));

#else  // ------- FFMA fallback (never runs on GB300) -------
    if (t < 128) {
        float q1r[64], q2r[64], out[64];
        for (int d = 0; d < 64; d++) {
            size_t idx = ((size_t)bh * kS + q0 + t) * kDK + d;
            q1r[d] = __bfloat162float(q1h[idx]) + __bfloat162float(q1l[idx]);
            q2r[d] = __bfloat162float(q2h[idx]) + __bfloat162float(q2l[idx]);
            out[d] = 0.f;
        }
        float m_i = -1e30f, l_i = 0.f;
        for (int j = 0; j < kS; j++) {
            const int blk = j >> 6, jr = j & 63;
            const size_t toff = ((size_t)bh * 16 + blk) * 4096;
            float s = 0.f, qv = 0.f;
            for (int d = 0; d < 64; d++) {
                uint32_t o = sw128((uint32_t)(jr * 128 + d * 2));
                float kr = __bfloat162float(*(const __nv_bfloat16*)((const char*)(krh + toff) + o))
                         + __bfloat162float(*(const __nv_bfloat16*)((const char*)(krl + toff) + o));
                float vr = __bfloat162float(*(const __nv_bfloat16*)((const char*)(vrh + toff) + o));
                s += q1r[d] * kr; qv += q2r[d] * vr;
            }
            if (mask[(size_t)b * kS * kS + (size_t)(q0 + t) * kS + j] == 0) s = -1.0e9f;
            float mnew = fmaxf(m_i, s);
            float scv = __expf(m_i - mnew), p = __expf(s - mnew);
            for (int d = 0; d < 64; d++) {
                uint32_t o = sw128((uint32_t)(d * 128 + jr * 2));
                float kv = __bfloat162float(*(const __nv_bfloat16*)((const char*)(kth + toff) + o))
                         + __bfloat162float(*(const __nv_bfloat16*)((const char*)(ktl + toff) + o));
                out[d] = out[d] * scv + p * qv * kv;
            }
            l_i = l_i * scv + p;
            m_i = mnew;
        }
        const float inv = 1.0f / l_i;
        for (int d = 0; d < 64; d++)
            outg[((size_t)b * kS + q0 + t) * kDM + h * 64 + d] = out[d] * inv;
    }
#endif
}

// ---------------------------------------------------------------------------
extern "C" void kernel_launch(void* const* d_in, const int* in_sizes, int n_in,
                              void* d_out, int out_size)
{
    (void)in_sizes; (void)n_in; (void)out_size;
    const float* query = (const float*)d_in[0];
    const float* key_  = (const float*)d_in[1];
    const float* value = (const float*)d_in[2];
    const int*   mask  = (const int*)  d_in[3];
    const float* Wq  = (const float*)d_in[4];  const float* bq  = (const float*)d_in[5];
    const float* Wk  = (const float*)d_in[6];  const float* bk  = (const float*)d_in[7];
    const float* Wv  = (const float*)d_in[8];  const float* bv  = (const float*)d_in[9];
    const float* Wo  = (const float*)d_in[10]; const float* bo  = (const float*)d_in[11];
    const float* Wkl = (const float*)d_in[12]; const float* bkl = (const float*)d_in[13];
    const float* Wql = (const float*)d_in[14]; const float* bql = (const float*)d_in[15];
    const float* Wq2 = (const float*)d_in[16]; const float* bq2 = (const float*)d_in[17];
    const float* Wvl = (const float*)d_in[18]; const float* bvl = (const float*)d_in[19];
    const float* Wel = (const float*)d_in[20]; const float* bel = (const float*)d_in[21];

    float *qh, *kh, *vh, *att;
    __nv_bfloat16 *krh, *krl, *vrh, *kth, *ktl, *q1h, *q1l, *q2h, *q2l;
    cudaGetSymbolAddress((void**)&qh,  g_qh);
    cudaGetSymbolAddress((void**)&kh,  g_kh);
    cudaGetSymbolAddress((void**)&vh,  g_vh);
    cudaGetSymbolAddress((void**)&att, g_att);
    cudaGetSymbolAddress((void**)&krh, g_krh);
    cudaGetSymbolAddress((void**)&krl, g_krl);
    cudaGetSymbolAddress((void**)&vrh, g_vrh);
    cudaGetSymbolAddress((void**)&kth, g_kth);
    cudaGetSymbolAddress((void**)&ktl, g_ktl);
    cudaGetSymbolAddress((void**)&q1h, g_q1h);
    cudaGetSymbolAddress((void**)&q1l, g_q1l);
    cudaGetSymbolAddress((void**)&q2h, g_q2h);
    cudaGetSymbolAddress((void**)&q2l, g_q2l);

    const int GEMM_SMEM = 66560;
    cudaFuncSetAttribute(tc_gemm, cudaFuncAttributeMaxDynamicSharedMemorySize, GEMM_SMEM);

    dim3 gg(8, 32);

    tc_gemm<<<gg, 256, GEMM_SMEM>>>(query, Wq, bq, qh, 1);
    tc_gemm<<<gg, 256, GEMM_SMEM>>>(key_,  Wk, bk, kh, 1);
    tc_gemm<<<gg, 256, GEMM_SMEM>>>(value, Wv, bv, vh, 1);

    const int CK_SMEM = 4 * 4096 * 4;
    const int FQ_SMEM = (4096 + 64*65 + 3*4096 + 4096) * 4;
    cudaFuncSetAttribute(conv_kv, cudaFuncAttributeMaxDynamicSharedMemorySize, CK_SMEM);
    cudaFuncSetAttribute(fused_q, cudaFuncAttributeMaxDynamicSharedMemorySize, FQ_SMEM);
    conv_kv<<<1024, 256, CK_SMEM>>>(kh, vh, Wkl, bkl, Wvl, bvl, krh, krl, vrh, kth, ktl);
    fused_q<<<1024, 256, FQ_SMEM>>>(qh, Wql, bql, Wel, bel, Wq2, bq2, q1h, q1l, q2h, q2l);

    // attention: 256 threads, 2 stages (80KB) + Pl (16KB) + red (1KB) + align
    const int ATT_SMEM = 100352;
    cudaFuncSetAttribute(attn_tc, cudaFuncAttributeMaxDynamicSharedMemorySize, ATT_SMEM);
    attn_tc<<<dim3(8, 64), 256, ATT_SMEM>>>(q1h, q1l, q2h, q2l,
                                            krh, krl, vrh, kth, ktl, mask, att);

    tc_gemm<<<gg, 256, GEMM_SMEM>>>(att, Wo, bo, (float*)d_out, 0);
}

// round 15
// speedup vs baseline: 1.0582x; 1.0582x over previous
#include <cuda_runtime.h>
#include <cuda_bf16.h>
#include <cstdint>

static constexpr int kB  = 4;
static constexpr int kS  = 1024;
static constexpr int kDM = 1024;
static constexpr int kH  = 16;
static constexpr int kDK = 64;
static constexpr int kBH = kB * kH;   // 64

// ---------------- scratch (static device globals; no allocation) ----------------
__device__ float g_qh [kBH * kS * kDK];
__device__ float g_kh [kBH * kS * kDK];
__device__ float g_vh [kBH * kS * kDK];
__device__ float g_att[kB * kS * kDM];

// bf16 tile buffers (SW128 tile-image layout, [bh][blk16][4096])
__device__ __nv_bfloat16 g_krh[kBH * 16 * 4096];
__device__ __nv_bfloat16 g_krl[kBH * 16 * 4096];
__device__ __nv_bfloat16 g_vrh[kBH * 16 * 4096];
__device__ __nv_bfloat16 g_kth[kBH * 16 * 4096];
__device__ __nv_bfloat16 g_ktl[kBH * 16 * 4096];
// bf16 linear [bh][s][d]
__device__ __nv_bfloat16 g_q1h[kBH * kS * kDK];
__device__ __nv_bfloat16 g_q1l[kBH * kS * kDK];
__device__ __nv_bfloat16 g_q2h[kBH * kS * kDK];
__device__ __nv_bfloat16 g_q2l[kBH * kS * kDK];

// ---------------------------------------------------------------------------
// helpers
// ---------------------------------------------------------------------------
__device__ __forceinline__ uint32_t smem_u32(const void* p) {
    uint32_t a;
    asm("{ .reg .u64 t; cvta.to.shared.u64 t, %1; cvt.u32.u64 %0, t; }" : "=r"(a) : "l"(p));
    return a;
}
__device__ __forceinline__ uint32_t pack_bf2(__nv_bfloat16 a, __nv_bfloat16 b) {
    __nv_bfloat162 t = __halves2bfloat162(a, b);
    return *reinterpret_cast<uint32_t*>(&t);
}
__device__ __forceinline__ uint32_t sw128(uint32_t o) { return o ^ ((o >> 3) & 0x70); }

#if defined(__CUDA_ARCH_FEAT_SM103_ALL) || !defined(__CUDA_ARCH__)
#define HAS_TCGEN05 1
#else
#define HAS_TCGEN05 0
#endif

#if HAS_TCGEN05
__device__ __forceinline__ void mbar_wait(uint32_t mbar, uint32_t parity) {
    asm volatile(
        "{\n\t.reg .pred P;\n\t"
        "LW%=:\n\t"
        "mbarrier.try_wait.parity.acquire.cta.shared::cta.b64 P, [%0], %1;\n\t"
        "@!P bra LW%=;\n\t}"
        :: "r"(mbar), "r"(parity) : "memory");
}

static constexpr uint32_t GE_IDESC =           // M=128, N=128
    (1u << 4) | (1u << 7) | (1u << 10) | ((128u / 8) << 17) | ((128u / 16) << 24);
static constexpr uint32_t AT_IDESC =           // M=128, N=64
    (1u << 4) | (1u << 7) | (1u << 10) | ((64u / 8) << 17) | ((128u / 16) << 24);

static constexpr uint64_t DESC_SW128 =
    (2ull << 61) | (1ull << 46) | (64ull << 32) | (1ull << 16);

__device__ __forceinline__ uint64_t mk_desc(uint32_t addr) {
    return DESC_SW128 | (uint64_t)((addr >> 4) & 0x3FFF);
}

__device__ __forceinline__ void mma_ss(uint32_t d, uint64_t ad, uint64_t bd,
                                       uint32_t idesc, bool en) {
    uint32_t e = en ? 1u : 0u;
    asm volatile(
        "{\n\t.reg .pred p;\n\t"
        "setp.ne.u32 p, %5, 0;\n\t"
        "tcgen05.mma.cta_group::1.kind::f16 [%0], %1, %2, %3, {%4, %4, %4, %4}, p;\n\t}"
        :: "r"(d), "l"(ad), "l"(bd), "r"(idesc), "r"(0u), "r"(e) : "memory");
}
__device__ __forceinline__ void mma_ts(uint32_t d, uint32_t at, uint64_t bd,
                                       uint32_t idesc, bool en) {
    uint32_t e = en ? 1u : 0u;
    asm volatile(
        "{\n\t.reg .pred p;\n\t"
        "setp.ne.u32 p, %5, 0;\n\t"
        "tcgen05.mma.cta_group::1.kind::f16 [%0], [%1], %2, %3, {%4, %4, %4, %4}, p;\n\t}"
        :: "r"(d), "r"(at), "l"(bd), "r"(idesc), "r"(0u), "r"(e) : "memory");
}

__device__ __forceinline__ void bulk_cp(uint32_t smem_dst, const void* gsrc,
                                        uint32_t bytes, uint32_t mbar) {
    asm volatile(
        "cp.async.bulk.shared::cta.global.mbarrier::complete_tx::bytes [%0], [%1], %2, [%3];"
        :: "r"(smem_dst), "l"(gsrc), "r"(bytes), "r"(mbar) : "memory");
}
__device__ __forceinline__ void mbar_expect(uint32_t mbar, uint32_t bytes) {
    asm volatile("mbarrier.arrive.expect_tx.shared.b64 _, [%0], %1;"
                 :: "r"(mbar), "r"(bytes) : "memory");
}

#define LDTM_X32(r, addr) \
    asm volatile( \
        "tcgen05.ld.sync.aligned.32x32b.x32.b32 " \
        "{%0, %1, %2, %3, %4, %5, %6, %7, " \
        " %8, %9, %10, %11, %12, %13, %14, %15, " \
        " %16, %17, %18, %19, %20, %21, %22, %23, " \
        " %24, %25, %26, %27, %28, %29, %30, %31}, [%32];" \
        : "=r"((r)[0]),  "=r"((r)[1]),  "=r"((r)[2]),  "=r"((r)[3]), \
          "=r"((r)[4]),  "=r"((r)[5]),  "=r"((r)[6]),  "=r"((r)[7]), \
          "=r"((r)[8]),  "=r"((r)[9]),  "=r"((r)[10]), "=r"((r)[11]), \
          "=r"((r)[12]), "=r"((r)[13]), "=r"((r)[14]), "=r"((r)[15]), \
          "=r"((r)[16]), "=r"((r)[17]), "=r"((r)[18]), "=r"((r)[19]), \
          "=r"((r)[20]), "=r"((r)[21]), "=r"((r)[22]), "=r"((r)[23]), \
          "=r"((r)[24]), "=r"((r)[25]), "=r"((r)[26]), "=r"((r)[27]), \
          "=r"((r)[28]), "=r"((r)[29]), "=r"((r)[30]), "=r"((r)[31]) \
        : "r"(addr))

#define TSTM_X32(addr, r) \
    asm volatile( \
        "tcgen05.st.sync.aligned.32x32b.x32.b32 [%0], " \
        "{%1, %2, %3, %4, %5, %6, %7, %8, " \
        " %9, %10, %11, %12, %13, %14, %15, %16, " \
        " %17, %18, %19, %20, %21, %22, %23, %24, " \
        " %25, %26, %27, %28, %29, %30, %31, %32};" \
        :: "r"(addr), \
           "r"((r)[0]),  "r"((r)[1]),  "r"((r)[2]),  "r"((r)[3]), \
           "r"((r)[4]),  "r"((r)[5]),  "r"((r)[6]),  "r"((r)[7]), \
           "r"((r)[8]),  "r"((r)[9]),  "r"((r)[10]), "r"((r)[11]), \
           "r"((r)[12]), "r"((r)[13]), "r"((r)[14]), "r"((r)[15]), \
           "r"((r)[16]), "r"((r)[17]), "r"((r)[18]), "r"((r)[19]), \
           "r"((r)[20]), "r"((r)[21]), "r"((r)[22]), "r"((r)[23]), \
           "r"((r)[24]), "r"((r)[25]), "r"((r)[26]), "r"((r)[27]), \
           "r"((r)[28]), "r"((r)[29]), "r"((r)[30]), "r"((r)[31]) \
        : "memory")
#endif  // HAS_TCGEN05

// convert float4 -> bf16 hi + bf16 residual, store 8B to each smem tile
__device__ __forceinline__ void store_hilo(float4 v, uint32_t hoff, uint32_t loff) {
    __nv_bfloat16 h0 = __float2bfloat16(v.x), h1 = __float2bfloat16(v.y);
    __nv_bfloat16 h2 = __float2bfloat16(v.z), h3 = __float2bfloat16(v.w);
    float r0 = v.x - __bfloat162float(h0), r1 = v.y - __bfloat162float(h1);
    float r2 = v.z - __bfloat162float(h2), r3 = v.w - __bfloat162float(h3);
    uint32_t hp0 = pack_bf2(h0, h1), hp1 = pack_bf2(h2, h3);
    uint32_t lp0 = pack_bf2(__float2bfloat16(r0), __float2bfloat16(r1));
    uint32_t lp1 = pack_bf2(__float2bfloat16(r2), __float2bfloat16(r3));
    asm volatile("st.shared.v2.b32 [%0], {%1, %2};" :: "r"(hoff), "r"(hp0), "r"(hp1) : "memory");
    asm volatile("st.shared.v2.b32 [%0], {%1, %2};" :: "r"(loff), "r"(lp0), "r"(lp1) : "memory");
}

// pack 8 floats -> uint4 of bf16 hi; and uint4 of residual lo
__device__ __forceinline__ uint4 pack_hi8(const float* f) {
    uint4 u;
    u.x = pack_bf2(__float2bfloat16(f[0]), __float2bfloat16(f[1]));
    u.y = pack_bf2(__float2bfloat16(f[2]), __float2bfloat16(f[3]));
    u.z = pack_bf2(__float2bfloat16(f[4]), __float2bfloat16(f[5]));
    u.w = pack_bf2(__float2bfloat16(f[6]), __float2bfloat16(f[7]));
    return u;
}
__device__ __forceinline__ uint4 pack_lo8(const float* f) {
    float r[8];
    #pragma unroll
    for (int i = 0; i < 8; i++)
        r[i] = f[i] - __bfloat162float(__float2bfloat16(f[i]));
    return pack_hi8(r);
}

// ---------------------------------------------------------------------------
// tc_gemm: C = A*W^T + bias, tcgen05 hi/lo.
// blockIdx.z selects among up to 3 (A, W, bias, out) sets — merges the three
// Q/K/V projections into ONE launch (kills 2 full wave-quantization tails).
// mode 0: out[m*1024+n]   mode 1: head-split
// ---------------------------------------------------------------------------
__global__ __launch_bounds__(256)
void tc_gemm(const float* __restrict__ A0, const float* __restrict__ A1,
             const float* __restrict__ A2,
             const float* __restrict__ W0, const float* __restrict__ W1,
             const float* __restrict__ W2,
             const float* __restrict__ b0, const float* __restrict__ b1,
             const float* __restrict__ b2,
             float* __restrict__ o0, float* __restrict__ o1, float* __restrict__ o2,
             int mode)
{
    extern __shared__ char dsm[];
    const int t   = threadIdx.x;
    const int m0  = blockIdx.y * 128;
    const int n0  = blockIdx.x * 128;
    const int z   = blockIdx.z;

    const float* A    = z == 0 ? A0 : (z == 1 ? A1 : A2);
    const float* W    = z == 0 ? W0 : (z == 1 ? W1 : W2);
    const float* bias = z == 0 ? b0 : (z == 1 ? b1 : b2);
    float*       out  = z == 0 ? o0 : (z == 1 ? o1 : o2);

#if HAS_TCGEN05
    __shared__ uint32_t s_tmem;
    __shared__ __align__(8) uint64_t s_mbar;

    const uint32_t base = (smem_u32(dsm) + 1023u) & ~1023u;
    const uint32_t ah = base, al = base + 16384, bhs = base + 32768, bls = base + 49152;
    const int wid = t >> 5;

    if (wid == 0) {
        asm volatile("tcgen05.alloc.cta_group::1.sync.aligned.shared::cta.b32 [%0], %1;"
                     :: "r"(smem_u32(&s_tmem)), "r"(128u) : "memory");
        asm volatile("tcgen05.relinquish_alloc_permit.cta_group::1.sync.aligned;");
    }
    if (t == 0)
        asm volatile("mbarrier.init.shared.b64 [%0], 1;" :: "r"(smem_u32(&s_mbar)) : "memory");
    __syncthreads();
    const uint32_t tmem = s_tmem;
    const uint32_t mbar = smem_u32(&s_mbar);

    const int ty = t >> 4, c4 = t & 15;
    const float* Ap = A + (size_t)(m0 + ty) * 1024 + c4 * 4;
    const float* Wp = W + (size_t)(n0 + ty) * 1024 + c4 * 4;

    int chunk = 0;
    for (int k0 = 0; k0 < 1024; k0 += 64, ++chunk) {
        float4 av[8], wv[8];
        #pragma unroll
        for (int i = 0; i < 8; i++) {
            av[i] = *(const float4*)(Ap + (size_t)(16 * i) * 1024 + k0);
            wv[i] = *(const float4*)(Wp + (size_t)(16 * i) * 1024 + k0);
        }
        if (chunk > 0) mbar_wait(mbar, (chunk - 1) & 1);
        #pragma unroll
        for (int i = 0; i < 8; i++) {
            uint32_t off = sw128((uint32_t)((ty + 16 * i) * 128 + c4 * 8));
            store_hilo(av[i], ah + off, al + off);
            store_hilo(wv[i], bhs + off, bls + off);
        }
        asm volatile("fence.proxy.async.shared::cta;" ::: "memory");
        __syncthreads();
        if (t == 0) {
            const uint64_t dah = mk_desc(ah),  dal = mk_desc(al);
            const uint64_t dbh = mk_desc(bhs), dbl = mk_desc(bls);
            #pragma unroll
            for (int ks = 0; ks < 4; ks++) {
                mma_ss(tmem, dah + 2 * ks, dbh + 2 * ks, GE_IDESC, !(chunk == 0 && ks == 0));
                mma_ss(tmem, dah + 2 * ks, dbl + 2 * ks, GE_IDESC, true);
                mma_ss(tmem, dal + 2 * ks, dbh + 2 * ks, GE_IDESC, true);
            }
            asm volatile(
                "tcgen05.commit.cta_group::1.mbarrier::arrive::one.shared::cluster.b64 [%0];"
                :: "r"(mbar) : "memory");
        }
    }
    mbar_wait(mbar, (16 - 1) & 1);
    __syncthreads();
    asm volatile("tcgen05.fence::after_thread_sync;" ::: "memory");

    if (wid < 4) {
        const int lane = t & 31;
        const int gr = m0 + wid * 32 + lane;
        for (int cb = 0; cb < 128; cb += 32) {
            uint32_t regs[32];
            LDTM_X32(regs, tmem + cb);
            asm volatile("tcgen05.wait::ld.sync.aligned;" ::: "memory");
            if (mode == 0) {
                float* op = out + (size_t)gr * 1024 + n0 + cb;
                #pragma unroll
                for (int c = 0; c < 32; c++)
                    op[c] = __uint_as_float(regs[c]) + bias[n0 + cb + c];
            } else {
                const int b = gr >> 10, s = gr & 1023;
                #pragma unroll
                for (int c = 0; c < 32; c++) {
                    const int gc = n0 + cb + c;
                    const int h = gc >> 6, d = gc & 63;
                    out[(((size_t)(b * kH + h)) * kS + s) * kDK + d] =
                        __uint_as_float(regs[c]) + bias[gc];
                }
            }
        }
    }
    __syncthreads();
    if (wid == 0)
        asm volatile("tcgen05.dealloc.cta_group::1.sync.aligned.b32 %0, %1;"
                     :: "r"(tmem), "r"(128u));
#else
    float* As = (float*)dsm;
    float* Bs = As + 16 * 128;
    const int tx = t & 15, ty = t >> 4;
    const int lm = t & 127;
    const int kb = (t >> 7) * 8;
    float acc[8][8];
    #pragma unroll
    for (int i = 0; i < 8; i++)
        #pragma unroll
        for (int j = 0; j < 8; j++) acc[i][j] = 0.f;
    for (int k0 = 0; k0 < 1024; k0 += 16) {
        const float4* Ag = (const float4*)(A + (size_t)(m0 + lm) * 1024 + k0 + kb);
        const float4* Wg = (const float4*)(W + (size_t)(n0 + lm) * 1024 + k0 + kb);
        float4 a0 = Ag[0], a1 = Ag[1];
        float4 b0v = Wg[0], b1v = Wg[1];
        As[(kb+0)*128+lm]=a0.x; As[(kb+1)*128+lm]=a0.y; As[(kb+2)*128+lm]=a0.z; As[(kb+3)*128+lm]=a0.w;
        As[(kb+4)*128+lm]=a1.x; As[(kb+5)*128+lm]=a1.y; As[(kb+6)*128+lm]=a1.z; As[(kb+7)*128+lm]=a1.w;
        Bs[(kb+0)*128+lm]=b0v.x; Bs[(kb+1)*128+lm]=b0v.y; Bs[(kb+2)*128+lm]=b0v.z; Bs[(kb+3)*128+lm]=b0v.w;
        Bs[(kb+4)*128+lm]=b1v.x; Bs[(kb+5)*128+lm]=b1v.y; Bs[(kb+6)*128+lm]=b1v.z; Bs[(kb+7)*128+lm]=b1v.w;
        __syncthreads();
        #pragma unroll
        for (int kk = 0; kk < 16; kk++) {
            float af[8], bf[8];
            #pragma unroll
            for (int i = 0; i < 8; i++) af[i] = As[kk*128 + ty + 16*i];
            #pragma unroll
            for (int j = 0; j < 8; j++) bf[j] = Bs[kk*128 + tx + 16*j];
            #pragma unroll
            for (int i = 0; i < 8; i++)
                #pragma unroll
                for (int j = 0; j < 8; j++) acc[i][j] += af[i] * bf[j];
        }
        __syncthreads();
    }
    #pragma unroll
    for (int i = 0; i < 8; i++) {
        const int r = m0 + ty + 16*i;
        #pragma unroll
        for (int j = 0; j < 8; j++) {
            const int c = n0 + tx + 16*j;
            float v = acc[i][j] + bias[c];
            if (mode == 0) out[(size_t)r * 1024 + c] = v;
            else {
                int b = r >> 10, s = r & 1023, h = c >> 6, d = c & 63;
                out[(((size_t)(b * kH + h)) * kS + s) * kDK + d] = v;
            }
        }
    }
#endif
}

// ---------------------------------------------------------------------------
// conv_kv: FFMA producer (proven R10 version)
// ---------------------------------------------------------------------------
__global__ __launch_bounds__(256)
void conv_kv(const float* __restrict__ Kh, const float* __restrict__ Vh,
             const float* __restrict__ Wkl, const float* __restrict__ bkl,
             const float* __restrict__ Wvl, const float* __restrict__ bvl,
             __nv_bfloat16* __restrict__ krh, __nv_bfloat16* __restrict__ krl,
             __nv_bfloat16* __restrict__ vrh,
             __nv_bfloat16* __restrict__ kth, __nv_bfloat16* __restrict__ ktl)
{
    extern __shared__ float fs[];
    float* W1 = fs;
    float* W2 = W1 + 4096;
    float* Xs = W2 + 4096;
    float* St = Xs + 4096;

    const int t  = threadIdx.x;
    const int tx = t & 15, ty = t >> 4;
    const int r0 = blockIdx.x * 64;
    const int lr = t & 63;
    const int kb = (t >> 6) * 16;
    const int bh = r0 >> 10, blkid = (r0 >> 6) & 15;
    const size_t tbase = ((size_t)bh * 16 + blkid) * 4096;
    const int wr = t >> 2, wq = t & 3;

    #pragma unroll
    for (int q = 0; q < 4; q++) {
        float4 w1 = *(const float4*)(Wkl + (size_t)lr * 64 + kb + 4*q);
        float4 w2 = *(const float4*)(Wvl + (size_t)lr * 64 + kb + 4*q);
        W1[(kb+4*q+0)*64+lr]=w1.x; W1[(kb+4*q+1)*64+lr]=w1.y; W1[(kb+4*q+2)*64+lr]=w1.z; W1[(kb+4*q+3)*64+lr]=w1.w;
        W2[(kb+4*q+0)*64+lr]=w2.x; W2[(kb+4*q+1)*64+lr]=w2.y; W2[(kb+4*q+2)*64+lr]=w2.z; W2[(kb+4*q+3)*64+lr]=w2.w;
    }

    // ---- pass 0: Kh -> kT tiles + kr tiles ----
    #pragma unroll
    for (int q = 0; q < 4; q++) {
        float4 x = *(const float4*)(Kh + (size_t)(r0 + lr) * 64 + kb + 4*q);
        Xs[(kb+4*q+0)*64+lr]=x.x; Xs[(kb+4*q+1)*64+lr]=x.y;
        Xs[(kb+4*q+2)*64+lr]=x.z; Xs[(kb+4*q+3)*64+lr]=x.w;
    }
    __syncthreads();

    {
        const int d = t & 63, seg = t >> 6;
        float f[16];
        #pragma unroll
        for (int i = 0; i < 16; i++) f[i] = Xs[d * 64 + seg * 16 + i];
        uint32_t o0 = (uint32_t)(d * 128 + seg * 32);
        uint32_t s0 = sw128(o0), s1 = sw128(o0 + 16);
        char* th = (char*)(kth + tbase);
        char* tl = (char*)(ktl + tbase);
        *(uint4*)(th + s0) = pack_hi8(f);     *(uint4*)(th + s1) = pack_hi8(f + 8);
        *(uint4*)(tl + s0) = pack_lo8(f);     *(uint4*)(tl + s1) = pack_lo8(f + 8);
    }

    {
        float acc[4][4];
        #pragma unroll
        for (int i = 0; i < 4; i++)
            #pragma unroll
            for (int j = 0; j < 4; j++) acc[i][j] = 0.f;
        #pragma unroll 16
        for (int kk = 0; kk < 64; kk++) {
            float af[4], bf[4];
            #pragma unroll
            for (int i = 0; i < 4; i++) af[i] = Xs[kk*64 + ty + 16*i];
            #pragma unroll
            for (int j = 0; j < 4; j++) bf[j] = W1[kk*64 + tx + 16*j];
            #pragma unroll
            for (int i = 0; i < 4; i++)
                #pragma unroll
                for (int j = 0; j < 4; j++) acc[i][j] += af[i] * bf[j];
        }
        #pragma unroll
        for (int i = 0; i < 4; i++)
            #pragma unroll
            for (int j = 0; j < 4; j++)
                St[(ty + 16*i) * 64 + tx + 16*j] = fmaxf(acc[i][j] + bkl[tx + 16*j], 0.f);
    }
    __syncthreads();
    {
        float f[16];
        #pragma unroll
        for (int i = 0; i < 16; i++) f[i] = St[wr * 64 + wq * 16 + i];
        uint32_t o0 = (uint32_t)(wr * 128 + wq * 32);
        uint32_t s0 = sw128(o0), s1 = sw128(o0 + 16);
        char* th = (char*)(krh + tbase);
        char* tl = (char*)(krl + tbase);
        *(uint4*)(th + s0) = pack_hi8(f);     *(uint4*)(th + s1) = pack_hi8(f + 8);
        *(uint4*)(tl + s0) = pack_lo8(f);     *(uint4*)(tl + s1) = pack_lo8(f + 8);
    }
    __syncthreads();

    // ---- pass 1: Vh -> vrh tiles ----
    #pragma unroll
    for (int q = 0; q < 4; q++) {
        float4 x = *(const float4*)(Vh + (size_t)(r0 + lr) * 64 + kb + 4*q);
        Xs[(kb+4*q+0)*64+lr]=x.x; Xs[(kb+4*q+1)*64+lr]=x.y;
        Xs[(kb+4*q+2)*64+lr]=x.z; Xs[(kb+4*q+3)*64+lr]=x.w;
    }
    __syncthreads();
    {
        float acc[4][4];
        #pragma unroll
        for (int i = 0; i < 4; i++)
            #pragma unroll
            for (int j = 0; j < 4; j++) acc[i][j] = 0.f;
        #pragma unroll 16
        for (int kk = 0; kk < 64; kk++) {
            float af[4], bf[4];
            #pragma unroll
            for (int i = 0; i < 4; i++) af[i] = Xs[kk*64 + ty + 16*i];
            #pragma unroll
            for (int j = 0; j < 4; j++) bf[j] = W2[kk*64 + tx + 16*j];
            #pragma unroll
            for (int i = 0; i < 4; i++)
                #pragma unroll
                for (int j = 0; j < 4; j++) acc[i][j] += af[i] * bf[j];
        }
        #pragma unroll
        for (int i = 0; i < 4; i++)
            #pragma unroll
            for (int j = 0; j < 4; j++)
                St[(ty + 16*i) * 64 + tx + 16*j] = fmaxf(acc[i][j] + bvl[tx + 16*j], 0.f);
    }
    __syncthreads();
    {
        float f[16];
        #pragma unroll
        for (int i = 0; i < 16; i++) f[i] = St[wr * 64 + wq * 16 + i];
        uint32_t o0 = (uint32_t)(wr * 128 + wq * 32);
        uint32_t s0 = sw128(o0), s1 = sw128(o0 + 16);
        char* th = (char*)(vrh + tbase);
        *(uint4*)(th + s0) = pack_hi8(f);     *(uint4*)(th + s1) = pack_hi8(f + 8);
    }
}

// ---------------------------------------------------------------------------
// fused_q: FFMA producer (proven R10 version)
// ---------------------------------------------------------------------------
__global__ __launch_bounds__(256)
void fused_q(const float* __restrict__ X,
             const float* __restrict__ Wql, const float* __restrict__ bql,
             const float* __restrict__ Wel, const float* __restrict__ bel,
             const float* __restrict__ Wq2, const float* __restrict__ bq2,
             __nv_bfloat16* __restrict__ q1h, __nv_bfloat16* __restrict__ q1l,
             __nv_bfloat16* __restrict__ q2h, __nv_bfloat16* __restrict__ q2l)
{
    extern __shared__ float fs[];
    float* Xs = fs;
    float* Ys = Xs + 4096;
    float* W1 = Ys + 64 * 65;
    float* W2 = W1 + 4096;
    float* W3 = W2 + 4096;
    float* St = W3 + 4096;

    const int t  = threadIdx.x;
    const int tx = t & 15, ty = t >> 4;
    const int r0 = blockIdx.x * 64;
    const int lr = t & 63;
    const int kb = (t >> 6) * 16;
    const int wr = t >> 2, wq = t & 3;

    #pragma unroll
    for (int q = 0; q < 4; q++) {
        float4 w1 = *(const float4*)(Wql + (size_t)lr * 64 + kb + 4*q);
        float4 w2 = *(const float4*)(Wel + (size_t)lr * 64 + kb + 4*q);
        float4 w3 = *(const float4*)(Wq2 + (size_t)lr * 64 + kb + 4*q);
        W1[(kb+4*q+0)*64+lr]=w1.x; W1[(kb+4*q+1)*64+lr]=w1.y; W1[(kb+4*q+2)*64+lr]=w1.z; W1[(kb+4*q+3)*64+lr]=w1.w;
        W2[(kb+4*q+0)*64+lr]=w2.x; W2[(kb+4*q+1)*64+lr]=w2.y; W2[(kb+4*q+2)*64+lr]=w2.z; W2[(kb+4*q+3)*64+lr]=w2.w;
        W3[(kb+4*q+0)*64+lr]=w3.x; W3[(kb+4*q+1)*64+lr]=w3.y; W3[(kb+4*q+2)*64+lr]=w3.z; W3[(kb+4*q+3)*64+lr]=w3.w;
        float4 x = *(const float4*)(X + (size_t)(r0 + lr) * 64 + kb + 4*q);
        Xs[(kb+4*q+0)*64+lr]=x.x; Xs[(kb+4*q+1)*64+lr]=x.y; Xs[(kb+4*q+2)*64+lr]=x.z; Xs[(kb+4*q+3)*64+lr]=x.w;
    }
    __syncthreads();

    // stage 1: q1a -> Ys
    {
        float acc[4][4];
        #pragma unroll
        for (int i = 0; i < 4; i++)
            #pragma unroll
            for (int j = 0; j < 4; j++) acc[i][j] = 0.f;
        #pragma unroll 16
        for (int kk = 0; kk < 64; kk++) {
            float af[4], bf[4];
            #pragma unroll
            for (int i = 0; i < 4; i++) af[i] = Xs[kk*64 + ty + 16*i];
            #pragma unroll
            for (int j = 0; j < 4; j++) bf[j] = W1[kk*64 + tx + 16*j];
            #pragma unroll
            for (int i = 0; i < 4; i++)
                #pragma unroll
                for (int j = 0; j < 4; j++) acc[i][j] += af[i] * bf[j];
        }
        #pragma unroll
        for (int i = 0; i < 4; i++)
            #pragma unroll
            for (int j = 0; j < 4; j++)
                Ys[(tx + 16*j) * 65 + ty + 16*i] = fmaxf(acc[i][j] + bql[tx + 16*j], 0.f);
    }

    // q2 -> St -> q2h/q2l
    {
        float acc[4][4];
        #pragma unroll
        for (int i = 0; i < 4; i++)
            #pragma unroll
            for (int j = 0; j < 4; j++) acc[i][j] = 0.f;
        #pragma unroll 16
        for (int kk = 0; kk < 64; kk++) {
            float af[4], bf[4];
            #pragma unroll
            for (int i = 0; i < 4; i++) af[i] = Xs[kk*64 + ty + 16*i];
            #pragma unroll
            for (int j = 0; j < 4; j++) bf[j] = W3[kk*64 + tx + 16*j];
            #pragma unroll
            for (int i = 0; i < 4; i++)
                #pragma unroll
                for (int j = 0; j < 4; j++) acc[i][j] += af[i] * bf[j];
        }
        __syncthreads();
        #pragma unroll
        for (int i = 0; i < 4; i++)
            #pragma unroll
            for (int j = 0; j < 4; j++)
                St[(ty + 16*i) * 64 + tx + 16*j] = fmaxf(acc[i][j] + bq2[tx + 16*j], 0.f);
    }
    __syncthreads();
    {
        float f[16];
        #pragma unroll
        for (int i = 0; i < 16; i++) f[i] = St[wr * 64 + wq * 16 + i];
        uint4* dh = (uint4*)(q2h + (size_t)(r0 + wr) * 64 + wq * 16);
        uint4* dl = (uint4*)(q2l + (size_t)(r0 + wr) * 64 + wq * 16);
        dh[0] = pack_hi8(f); dh[1] = pack_hi8(f + 8);
        dl[0] = pack_lo8(f); dl[1] = pack_lo8(f + 8);
    }
    __syncthreads();

    // q1 from Ys -> St -> q1h/q1l
    {
        float acc[4][4];
        #pragma unroll
        for (int i = 0; i < 4; i++)
            #pragma unroll
            for (int j = 0; j < 4; j++) acc[i][j] = 0.f;
        #pragma unroll 16
        for (int kk = 0; kk < 64; kk++) {
            float af[4], bf[4];
            #pragma unroll
            for (int i = 0; i < 4; i++) af[i] = Ys[kk*65 + ty + 16*i];
            #pragma unroll
            for (int j = 0; j < 4; j++) bf[j] = W2[kk*64 + tx + 16*j];
            #pragma unroll
            for (int i = 0; i < 4; i++)
                #pragma unroll
                for (int j = 0; j < 4; j++) acc[i][j] += af[i] * bf[j];
        }
        #pragma unroll
        for (int i = 0; i < 4; i++)
            #pragma unroll
            for (int j = 0; j < 4; j++)
                St[(ty + 16*i) * 64 + tx + 16*j] = fmaxf(acc[i][j] + bel[tx + 16*j], 0.f);
    }
    __syncthreads();
    {
        float f[16];
        #pragma unroll
        for (int i = 0; i < 16; i++) f[i] = St[wr * 64 + wq * 16 + i];
        uint4* dh = (uint4*)(q1h + (size_t)(r0 + wr) * 64 + wq * 16);
        uint4* dl = (uint4*)(q1l + (size_t)(r0 + wr) * 64 + wq * 16);
        dh[0] = pack_hi8(f); dh[1] = pack_hi8(f + 8);
        dl[0] = pack_lo8(f); dl[1] = pack_lo8(f + 8);
    }
}

// ---------------------------------------------------------------------------
// attn v5 (exact R10 champion): pipelined tcgen05 attention, Ph aliased into
// the dead krh/krl region of the current stage. 128 threads, 2 CTAs/SM.
// TMEM (256): Q1H@0 Q1L@32 Q2H@64 Q2L@96 | TQV@128 | TS/TPK@192
// ---------------------------------------------------------------------------
__global__ __launch_bounds__(128, 2)
void attn_tc(const __nv_bfloat16* __restrict__ q1h, const __nv_bfloat16* __restrict__ q1l,
             const __nv_bfloat16* __restrict__ q2h, const __nv_bfloat16* __restrict__ q2l,
             const __nv_bfloat16* __restrict__ krh, const __nv_bfloat16* __restrict__ krl,
             const __nv_bfloat16* __restrict__ vrh,
             const __nv_bfloat16* __restrict__ kth, const __nv_bfloat16* __restrict__ ktl,
             const int* __restrict__ mask, float* __restrict__ outg)
{
    const int t  = threadIdx.x;
    const int bh = blockIdx.y;
    const int q0 = blockIdx.x * 128;
    const int b  = bh >> 4, h = bh & 15;

#if HAS_TCGEN05
    extern __shared__ char dsm[];
    __shared__ uint32_t s_tmem;
    __shared__ __align__(8) uint64_t s_mb[4];   // 0:sq 1:pk 2:ld0 3:ld1

    const uint32_t base = (smem_u32(dsm) + 1023u) & ~1023u;
    const uint32_t stg[2] = { base, base + 40960 };
    const uint32_t Pl = base + 81920;

    const int wid = t >> 5;
    if (wid == 0) {
        asm volatile("tcgen05.alloc.cta_group::1.sync.aligned.shared::cta.b32 [%0], %1;"
                     :: "r"(smem_u32(&s_tmem)), "r"(256u) : "memory");
        asm volatile("tcgen05.relinquish_alloc_permit.cta_group::1.sync.aligned;");
    }
    if (t == 0) {
        #pragma unroll
        for (int i = 0; i < 4; i++)
            asm volatile("mbarrier.init.shared.b64 [%0], 1;"
                         :: "r"(smem_u32(&s_mb[i])) : "memory");
    }
    __syncthreads();
    const uint32_t tmem = s_tmem;
    const uint32_t mb_sq = smem_u32(&s_mb[0]), mb_pk = smem_u32(&s_mb[1]);
    const uint32_t mb_ld[2] = { smem_u32(&s_mb[2]), smem_u32(&s_mb[3]) };
    const uint32_t Q1H = tmem, Q1L = tmem + 32, Q2H = tmem + 64, Q2L = tmem + 96;
    const uint32_t TQV = tmem + 128, TS = tmem + 192;
    const uint32_t warp_off = (uint32_t)(t >> 5) << 21;

    const size_t tb = (size_t)bh * 16;

    if (t == 0) {
        asm volatile("fence.proxy.async.shared::cta;" ::: "memory");
        #pragma unroll
        for (int s = 0; s < 2; s++) {
            mbar_expect(mb_ld[s], 40960);
            const size_t off = (tb + s) * 4096;
            bulk_cp(stg[s] + 0,     (const char*)(krh + off), 8192, mb_ld[s]);
            bulk_cp(stg[s] + 8192,  (const char*)(krl + off), 8192, mb_ld[s]);
            bulk_cp(stg[s] + 16384, (const char*)(vrh + off), 8192, mb_ld[s]);
            bulk_cp(stg[s] + 24576, (const char*)(kth + off), 8192, mb_ld[s]);
            bulk_cp(stg[s] + 32768, (const char*)(ktl + off), 8192, mb_ld[s]);
        }
    }

    {
        uint32_t r[32];
        const uint4* p = (const uint4*)(q1h + ((size_t)bh * kS + q0 + t) * kDK);
        #pragma unroll
        for (int i = 0; i < 8; i++) { uint4 v = p[i];
            r[4*i]=v.x; r[4*i+1]=v.y; r[4*i+2]=v.z; r[4*i+3]=v.w; }
        TSTM_X32(Q1H + warp_off, r);
        p = (const uint4*)(q1l + ((size_t)bh * kS + q0 + t) * kDK);
        #pragma unroll
        for (int i = 0; i < 8; i++) { uint4 v = p[i];
            r[4*i]=v.x; r[4*i+1]=v.y; r[4*i+2]=v.z; r[4*i+3]=v.w; }
        TSTM_X32(Q1L + warp_off, r);
        p = (const uint4*)(q2h + ((size_t)bh * kS + q0 + t) * kDK);
        #pragma unroll
        for (int i = 0; i < 8; i++) { uint4 v = p[i];
            r[4*i]=v.x; r[4*i+1]=v.y; r[4*i+2]=v.z; r[4*i+3]=v.w; }
        TSTM_X32(Q2H + warp_off, r);
        p = (const uint4*)(q2l + ((size_t)bh * kS + q0 + t) * kDK);
        #pragma unroll
        for (int i = 0; i < 8; i++) { uint4 v = p[i];
            r[4*i]=v.x; r[4*i+1]=v.y; r[4*i+2]=v.z; r[4*i+3]=v.w; }
        TSTM_X32(Q2L + warp_off, r);
        asm volatile("tcgen05.wait::st.sync.aligned;" ::: "memory");
    }
    asm volatile("tcgen05.fence::before_thread_sync;" ::: "memory");
    __syncthreads();

    if (t == 0) {
        asm volatile("tcgen05.fence::after_thread_sync;" ::: "memory");
        mbar_wait(mb_ld[0], 0);
        const uint64_t dkh = mk_desc(stg[0]), dkl = mk_desc(stg[0] + 8192);
        const uint64_t dvh = mk_desc(stg[0] + 16384);
        #pragma unroll
        for (int ks = 0; ks < 4; ks++) {
            mma_ts(TS,  Q1H + ks*8, dkh + 2*ks, AT_IDESC, ks > 0);
            mma_ts(TS,  Q1H + ks*8, dkl + 2*ks, AT_IDESC, true);
            mma_ts(TS,  Q1L + ks*8, dkh + 2*ks, AT_IDESC, true);
            mma_ts(TQV, Q2H + ks*8, dvh + 2*ks, AT_IDESC, ks > 0);
            mma_ts(TQV, Q2L + ks*8, dvh + 2*ks, AT_IDESC, true);
        }
        asm volatile(
            "tcgen05.commit.cta_group::1.mbarrier::arrive::one.shared::cluster.b64 [%0];"
            :: "r"(mb_sq) : "memory");
    }

    float out[64];
    #pragma unroll
    for (int c = 0; c < 64; c++) out[c] = 0.f;
    float m_i = -1e30f, l_i = 0.f;

    for (int blk = 0; blk < 16; blk++) {
        const int st = blk & 1;
        const int k0 = blk * 64;
        const uint32_t Ph = stg[st];

        mbar_wait(mb_sq, blk & 1);
        asm volatile("tcgen05.fence::after_thread_sync;" ::: "memory");

        uint32_t sr[64];
        LDTM_X32(sr, TS);
        LDTM_X32(sr + 32, TS + 32);
        asm volatile("tcgen05.wait::ld.sync.aligned;" ::: "memory");

        const int4* mp = (const int4*)(mask + (size_t)b * kS * kS + (size_t)(q0 + t) * kS + k0);
        #pragma unroll
        for (int j4 = 0; j4 < 16; j4++) {
            int4 mv = mp[j4];
            if (mv.x == 0) sr[4*j4+0] = __float_as_uint(-1.0e9f);
            if (mv.y == 0) sr[4*j4+1] = __float_as_uint(-1.0e9f);
            if (mv.z == 0) sr[4*j4+2] = __float_as_uint(-1.0e9f);
            if (mv.w == 0) sr[4*j4+3] = __float_as_uint(-1.0e9f);
        }

        float rmax = -1e30f;
        #pragma unroll
        for (int j = 0; j < 64; j++) rmax = fmaxf(rmax, __uint_as_float(sr[j]));
        const float mnew = fmaxf(m_i, rmax);
        const float sc   = __expf(m_i - mnew);
        float rsum = 0.f;

        #pragma unroll
        for (int half = 0; half < 2; half++) {
            uint32_t qr[32];
            LDTM_X32(qr, TQV + 32 * half);
            asm volatile("tcgen05.wait::ld.sync.aligned;" ::: "memory");
            #pragma unroll
            for (int j = 0; j < 32; j++) {
                float p = __expf(__uint_as_float(sr[32*half + j]) - mnew);
                rsum += p;
                sr[32*half + j] = __float_as_uint(p * __uint_as_float(qr[j]));
            }
        }
        m_i = mnew;
        l_i = l_i * sc + rsum;

        #pragma unroll
        for (int c = 0; c < 8; c++) {
            float f[8];
            #pragma unroll
            for (int j = 0; j < 8; j++) f[j] = __uint_as_float(sr[8*c + j]);
            uint4 uh = pack_hi8(f);
            uint4 ul = pack_lo8(f);
            uint32_t off = sw128((uint32_t)(t * 128 + c * 16));
            asm volatile("st.shared.v4.b32 [%0], {%1,%2,%3,%4};"
                         :: "r"(Ph + off), "r"(uh.x), "r"(uh.y), "r"(uh.z), "r"(uh.w) : "memory");
            asm volatile("st.shared.v4.b32 [%0], {%1,%2,%3,%4};"
                         :: "r"(Pl + off), "r"(ul.x), "r"(ul.y), "r"(ul.z), "r"(ul.w) : "memory");
        }
        #pragma unroll
        for (int c = 0; c < 64; c++) out[c] *= sc;

        asm volatile("tcgen05.fence::before_thread_sync;" ::: "memory");
        asm volatile("fence.proxy.async.shared::cta;" ::: "memory");
        __syncthreads();

        if (t == 0) {
            asm volatile("tcgen05.fence::after_thread_sync;" ::: "memory");
            const uint64_t dPh = mk_desc(Ph), dPl = mk_desc(Pl);
            const uint64_t dth = mk_desc(stg[st] + 24576), dtl = mk_desc(stg[st] + 32768);
            #pragma unroll
            for (int ks = 0; ks < 4; ks++) {
                mma_ss(TS, dPh + 2*ks, dth + 2*ks, AT_IDESC, ks > 0);
                mma_ss(TS, dPh + 2*ks, dtl + 2*ks, AT_IDESC, true);
                mma_ss(TS, dPl + 2*ks, dth + 2*ks, AT_IDESC, true);
            }
            asm volatile(
                "tcgen05.commit.cta_group::1.mbarrier::arrive::one.shared::cluster.b64 [%0];"
                :: "r"(mb_pk) : "memory");
        }
        mbar_wait(mb_pk, blk & 1);
        asm volatile("tcgen05.fence::after_thread_sync;" ::: "memory");

        uint32_t pr[64];
        LDTM_X32(pr, TS);
        LDTM_X32(pr + 32, TS + 32);
        asm volatile("tcgen05.wait::ld.sync.aligned;" ::: "memory");
        asm volatile("tcgen05.fence::before_thread_sync;" ::: "memory");
        __syncthreads();

        if (t == 0) {
            if (blk + 2 < 16) {
                mbar_expect(mb_ld[st], 40960);
                const size_t off = (tb + blk + 2) * 4096;
                bulk_cp(stg[st] + 0,     (const char*)(krh + off), 8192, mb_ld[st]);
                bulk_cp(stg[st] + 8192,  (const char*)(krl + off), 8192, mb_ld[st]);
                bulk_cp(stg[st] + 16384, (const char*)(vrh + off), 8192, mb_ld[st]);
                bulk_cp(stg[st] + 24576, (const char*)(kth + off), 8192, mb_ld[st]);
                bulk_cp(stg[st] + 32768, (const char*)(ktl + off), 8192, mb_ld[st]);
            }
            if (blk + 1 < 16) {
                asm volatile("tcgen05.fence::after_thread_sync;" ::: "memory");
                mbar_wait(mb_ld[1 - st], ((blk + 1) >> 1) & 1);
                const uint32_t sb = stg[1 - st];
                const uint64_t dkh = mk_desc(sb), dkl = mk_desc(sb + 8192);
                const uint64_t dvh = mk_desc(sb + 16384);
                #pragma unroll
                for (int ks = 0; ks < 4; ks++) {
                    mma_ts(TS,  Q1H + ks*8, dkh + 2*ks, AT_IDESC, ks > 0);
                    mma_ts(TS,  Q1H + ks*8, dkl + 2*ks, AT_IDESC, true);
                    mma_ts(TS,  Q1L + ks*8, dkh + 2*ks, AT_IDESC, true);
                    mma_ts(TQV, Q2H + ks*8, dvh + 2*ks, AT_IDESC, ks > 0);
                    mma_ts(TQV, Q2L + ks*8, dvh + 2*ks, AT_IDESC, true);
                }
                asm volatile(
                    "tcgen05.commit.cta_group::1.mbarrier::arrive::one.shared::cluster.b64 [%0];"
                    :: "r"(mb_sq) : "memory");
            }
        }

        #pragma unroll
        for (int j = 0; j < 64; j++) out[j] += __uint_as_float(pr[j]);
    }

    const float inv = 1.0f / l_i;
    float4* op = (float4*)(outg + ((size_t)b * kS + q0 + t) * kDM + h * 64);
    #pragma unroll
    for (int c4 = 0; c4 < 16; c4++) {
        float4 v;
        v.x = out[4*c4+0] * inv; v.y = out[4*c4+1] * inv;
        v.z = out[4*c4+2] * inv; v.w = out[4*c4+3] * inv;
        op[c4] = v;
    }
    __syncthreads();
    if (wid == 0)
        asm volatile("tcgen05.dealloc.cta_group::1.sync.aligned.b32 %0, %1;"
                     :: "r"(tmem), "r"(256u));

#else  // ------- FFMA fallback (never runs on GB300) -------
    float q1r[64], q2r[64], out[64];
    for (int d = 0; d < 64; d++) {
        size_t idx = ((size_t)bh * kS + q0 + t) * kDK + d;
        q1r[d] = __bfloat162float(q1h[idx]) + __bfloat162float(q1l[idx]);
        q2r[d] = __bfloat162float(q2h[idx]) + __bfloat162float(q2l[idx]);
        out[d] = 0.f;
    }
    float m_i = -1e30f, l_i = 0.f;
    for (int j = 0; j < kS; j++) {
        const int blk = j >> 6, jr = j & 63;
        const size_t toff = ((size_t)bh * 16 + blk) * 4096;
        float s = 0.f, qv = 0.f;
        for (int d = 0; d < 64; d++) {
            uint32_t o = sw128((uint32_t)(jr * 128 + d * 2));
            float kr = __bfloat162float(*(const __nv_bfloat16*)((const char*)(krh + toff) + o))
                     + __bfloat162float(*(const __nv_bfloat16*)((const char*)(krl + toff) + o));
            float vr = __bfloat162float(*(const __nv_bfloat16*)((const char*)(vrh + toff) + o));
            s += q1r[d] * kr; qv += q2r[d] * vr;
        }
        if (mask[(size_t)b * kS * kS + (size_t)(q0 + t) * kS + j] == 0) s = -1.0e9f;
        float mnew = fmaxf(m_i, s);
        float scv = __expf(m_i - mnew), p = __expf(s - mnew);
        for (int d = 0; d < 64; d++) {
            uint32_t o = sw128((uint32_t)(d * 128 + jr * 2));
            float kv = __bfloat162float(*(const __nv_bfloat16*)((const char*)(kth + toff) + o))
                     + __bfloat162float(*(const __nv_bfloat16*)((const char*)(ktl + toff) + o));
            out[d] = out[d] * scv + p * qv * kv;
        }
        l_i = l_i * scv + p;
        m_i = mnew;
    }
    const float inv = 1.0f / l_i;
    for (int d = 0; d < 64; d++)
        outg[((size_t)b * kS + q0 + t) * kDM + h * 64 + d] = out[d] * inv;
#endif
}

// ---------------------------------------------------------------------------
extern "C" void kernel_launch(void* const* d_in, const int* in_sizes, int n_in,
                              void* d_out, int out_size)
{
    (void)in_sizes; (void)n_in; (void)out_size;
    const float* query = (const float*)d_in[0];
    const float* key_  = (const float*)d_in[1];
    const float* value = (const float*)d_in[2];
    const int*   mask  = (const int*)  d_in[3];
    const float* Wq  = (const float*)d_in[4];  const float* bq  = (const float*)d_in[5];
    const float* Wk  = (const float*)d_in[6];  const float* bk  = (const float*)d_in[7];
    const float* Wv  = (const float*)d_in[8];  const float* bv  = (const float*)d_in[9];
    const float* Wo  = (const float*)d_in[10]; const float* bo  = (const float*)d_in[11];
    const float* Wkl = (const float*)d_in[12]; const float* bkl = (const float*)d_in[13];
    const float* Wql = (const float*)d_in[14]; const float* bql = (const float*)d_in[15];
    const float* Wq2 = (const float*)d_in[16]; const float* bq2 = (const float*)d_in[17];
    const float* Wvl = (const float*)d_in[18]; const float* bvl = (const float*)d_in[19];
    const float* Wel = (const float*)d_in[20]; const float* bel = (const float*)d_in[21];

    float *qh, *kh, *vh, *att;
    __nv_bfloat16 *krh, *krl, *vrh, *kth, *ktl, *q1h, *q1l, *q2h, *q2l;
    cudaGetSymbolAddress((void**)&qh,  g_qh);
    cudaGetSymbolAddress((void**)&kh,  g_kh);
    cudaGetSymbolAddress((void**)&vh,  g_vh);
    cudaGetSymbolAddress((void**)&att, g_att);
    cudaGetSymbolAddress((void**)&krh, g_krh);
    cudaGetSymbolAddress((void**)&krl, g_krl);
    cudaGetSymbolAddress((void**)&vrh, g_vrh);
    cudaGetSymbolAddress((void**)&kth, g_kth);
    cudaGetSymbolAddress((void**)&ktl, g_ktl);
    cudaGetSymbolAddress((void**)&q1h, g_q1h);
    cudaGetSymbolAddress((void**)&q1l, g_q1l);
    cudaGetSymbolAddress((void**)&q2h, g_q2h);
    cudaGetSymbolAddress((void**)&q2l, g_q2l);

    const int GEMM_SMEM = 66560;
    cudaFuncSetAttribute(tc_gemm, cudaFuncAttributeMaxDynamicSharedMemorySize, GEMM_SMEM);

    // Q/K/V projections merged into ONE launch (grid.z selects operand set)
    tc_gemm<<<dim3(8, 32, 3), 256, GEMM_SMEM>>>(
        query, key_, value, Wq, Wk, Wv, bq, bk, bv, qh, kh, vh, 1);

    const int CK_SMEM = 4 * 4096 * 4;
    const int FQ_SMEM = (4096 + 64*65 + 3*4096 + 4096) * 4;
    cudaFuncSetAttribute(conv_kv, cudaFuncAttributeMaxDynamicSharedMemorySize, CK_SMEM);
    cudaFuncSetAttribute(fused_q, cudaFuncAttributeMaxDynamicSharedMemorySize, FQ_SMEM);
    conv_kv<<<1024, 256, CK_SMEM>>>(kh, vh, Wkl, bkl, Wvl, bvl, krh, krl, vrh, kth, ktl);
    fused_q<<<1024, 256, FQ_SMEM>>>(qh, Wql, bql, Wel, bel, Wq2, bq2, q1h, q1l, q2h, q2l);

    const int ATT_SMEM = 99328;   // 2 stages (80KB) + Pl (16KB) + align; Ph aliased
    cudaFuncSetAttribute(attn_tc, cudaFuncAttributeMaxDynamicSharedMemorySize, ATT_SMEM);
    attn_tc<<<dim3(8, 64), 128, ATT_SMEM>>>(q1h, q1l, q2h, q2l,
                                            krh, krl, vrh, kth, ktl, mask, att);

    // output projection (single set; z=1)
    tc_gemm<<<dim3(8, 32, 1), 256, GEMM_SMEM>>>(
        att, att, att, Wo, Wo, Wo, bo, bo, bo,
        (float*)d_out, (float*)d_out, (float*)d_out, 0);
}